// round 1
// baseline (speedup 1.0000x reference)
#include <cuda_runtime.h>
#include <math.h>

// ---------------------------------------------------------------------------
// ActivationPNALayer: fused PNA aggregation + tower + 2x BatchNorm
// Inputs (metadata order):
//  0: h      [N*D]  f32
//  1: ef     [E*D]  f32
//  2: norm   [N]    f32
//  3: gamma1 [D]    f32
//  4: beta1  [D]    f32
//  5: gamma2 [D]    f32
//  6: beta2  [D]    f32
//  7: src    [E]    i32
//  8: dst    [E]    i32
// Output: [N*D] f32
// ---------------------------------------------------------------------------

#define N_MAX 100000
#define E_MAX 1600000
#define DD 64
#define AVG_D_LOG 2.8332133440562162f
#define EPS_STD 1e-5f
#define EPS_BN 1e-5f

#define SCAN_T 512
#define SCAN_BMAX 256

// scratch (device globals: allocation-free)
__device__ float g_hin[N_MAX * DD];
__device__ float g_ht[N_MAX * DD];
__device__ int   g_deg[N_MAX];
__device__ int   g_off[N_MAX + 1];
__device__ int   g_cur[N_MAX];
__device__ int   g_eids[E_MAX];
__device__ int   g_part[SCAN_BMAX];
__device__ float g_s1[DD], g_s2[DD], g_t1[DD], g_t2[DD];
__device__ float g_A1[DD], g_B1[DD], g_A2[DD], g_B2[DD];

// ---------------------------------------------------------------- zero scratch
__global__ void zero_kernel(int n) {
    int total = gridDim.x * blockDim.x;
    int i = blockIdx.x * blockDim.x + threadIdx.x;
    for (int k = i; k < n; k += total) { g_deg[k] = 0; g_cur[k] = 0; }
    if (i < DD) { g_s1[i] = 0.f; g_s2[i] = 0.f; g_t1[i] = 0.f; g_t2[i] = 0.f; }
}

// ---------------------------------------------------------------- h_in = h*norm
__global__ void hin_kernel(const float4* __restrict__ h4,
                           const float* __restrict__ norm, int n) {
    int total = gridDim.x * blockDim.x;
    int nq = n * (DD / 4);                       // float4 elems
    float4* o4 = (float4*)g_hin;
    for (int i = blockIdx.x * blockDim.x + threadIdx.x; i < nq; i += total) {
        int row = i >> 4;                        // DD/4 = 16 per row
        float nv = __ldg(&norm[row]);
        float4 v = h4[i];
        v.x *= nv; v.y *= nv; v.z *= nv; v.w *= nv;
        o4[i] = v;
    }
}

// ---------------------------------------------------------------- degree count
__global__ void deg_kernel(const int* __restrict__ dst, int e) {
    int total = gridDim.x * blockDim.x;
    for (int i = blockIdx.x * blockDim.x + threadIdx.x; i < e; i += total)
        atomicAdd(&g_deg[dst[i]], 1);
}

// ---------------------------------------------------------------- scan (3 steps)
__global__ void scan1_kernel(int n) {
    __shared__ int sh[SCAN_T];
    int i = blockIdx.x * SCAN_T + threadIdx.x;
    sh[threadIdx.x] = (i < n) ? g_deg[i] : 0;
    __syncthreads();
    for (int s = SCAN_T / 2; s > 0; s >>= 1) {
        if (threadIdx.x < s) sh[threadIdx.x] += sh[threadIdx.x + s];
        __syncthreads();
    }
    if (threadIdx.x == 0) g_part[blockIdx.x] = sh[0];
}

__global__ void scan2_kernel(int nb) {
    if (threadIdx.x == 0 && blockIdx.x == 0) {
        int acc = 0;
        for (int i = 0; i < nb; i++) { int t = g_part[i]; g_part[i] = acc; acc += t; }
    }
}

__global__ void scan3_kernel(int n, int e_total) {
    __shared__ int sh[SCAN_T];
    int i = blockIdx.x * SCAN_T + threadIdx.x;
    int v = (i < n) ? g_deg[i] : 0;
    sh[threadIdx.x] = v;
    __syncthreads();
    for (int s = 1; s < SCAN_T; s <<= 1) {
        int t = (threadIdx.x >= s) ? sh[threadIdx.x - s] : 0;
        __syncthreads();
        sh[threadIdx.x] += t;
        __syncthreads();
    }
    int excl = sh[threadIdx.x] - v + g_part[blockIdx.x];
    if (i < n) g_off[i] = excl;
    if (i == 0) g_off[n] = e_total;
}

// ---------------------------------------------------------------- CSR scatter
__global__ void scatter_kernel(const int* __restrict__ dst, int e) {
    int total = gridDim.x * blockDim.x;
    for (int i = blockIdx.x * blockDim.x + threadIdx.x; i < e; i += total) {
        int d = dst[i];
        int pos = atomicAdd(&g_cur[d], 1);
        g_eids[g_off[d] + pos] = i;
    }
}

// ---------------------------------------------------------------- aggregation
// one warp per node; lane owns dims (2*lane, 2*lane+1) as float2
__global__ void __launch_bounds__(256) agg_kernel(
    const float2* __restrict__ ef2, const int* __restrict__ src, int n) {
    const int lane = threadIdx.x & 31;
    const int wpb = blockDim.x >> 5;
    int warpGlobal = blockIdx.x * wpb + (threadIdx.x >> 5);
    int warpStride = gridDim.x * wpb;

    const float2* hin2 = (const float2*)g_hin;
    float2* ht2 = (float2*)g_ht;

    float a10 = 0.f, a11 = 0.f, a20 = 0.f, a21 = 0.f;  // BN1 stats accum

    for (int node = warpGlobal; node < n; node += warpStride) {
        int start = g_off[node];
        int end = g_off[node + 1];
        float2 hd = hin2[node * 32 + lane];

        float s0 = 0.f, s1 = 0.f, q0 = 0.f, q1 = 0.f;
        float mx0 = -INFINITY, mx1 = -INFINITY;
        float mn0 = INFINITY, mn1 = INFINITY;

        for (int base = start; base < end; base += 32) {
            int m = min(32, end - base);
            int e = 0, sv = 0;
            if (lane < m) { e = g_eids[base + lane]; sv = src[e]; }
            for (int j = 0; j < m; j++) {
                int ej = __shfl_sync(0xffffffffu, e, j);
                int sj = __shfl_sync(0xffffffffu, sv, j);
                float2 hs = hin2[sj * 32 + lane];
                float2 ev = __ldg(&ef2[ej * 32 + lane]);
                float z0 = hs.x + hd.x + ev.x;
                float z1 = hs.y + hd.y + ev.y;
                s0 += z0; q0 = fmaf(z0, z0, q0);
                mx0 = fmaxf(mx0, z0); mn0 = fminf(mn0, z0);
                s1 += z1; q1 = fmaf(z1, z1, q1);
                mx1 = fmaxf(mx1, z1); mn1 = fminf(mn1, z1);
            }
        }

        float fdeg = (float)(end - start);
        float inv = 1.0f / fdeg;
        float mean0 = s0 * inv, mean1 = s1 * inv;
        float var0 = fmaxf(q0 * inv - mean0 * mean0, 0.f);
        float var1 = fmaxf(q1 * inv - mean1 * mean1, 0.f);
        float std0 = sqrtf(var0 + EPS_STD);
        float std1 = sqrtf(var1 + EPS_STD);
        float logd = logf(fdeg + 1.0f);
        float c = 1.0f + logd * (1.0f / AVG_D_LOG) + AVG_D_LOG / logd;
        float p0 = (hd.x + (mean0 + mx0 + mn0 + std0) * c) * (1.0f / 13.0f);
        float p1 = (hd.y + (mean1 + mx1 + mn1 + std1) * c) * (1.0f / 13.0f);
        ht2[node * 32 + lane] = make_float2(p0, p1);

        a10 += p0; a11 += p1;
        a20 = fmaf(p0, p0, a20); a21 = fmaf(p1, p1, a21);
    }

    // hierarchical BN1-stat reduction: regs -> shared -> global atomics
    __shared__ float sh1[DD], sh2[DD];
    if (threadIdx.x < DD) { sh1[threadIdx.x] = 0.f; sh2[threadIdx.x] = 0.f; }
    __syncthreads();
    atomicAdd(&sh1[2 * lane], a10);
    atomicAdd(&sh1[2 * lane + 1], a11);
    atomicAdd(&sh2[2 * lane], a20);
    atomicAdd(&sh2[2 * lane + 1], a21);
    __syncthreads();
    if (threadIdx.x < DD) {
        atomicAdd(&g_s1[threadIdx.x], sh1[threadIdx.x]);
        atomicAdd(&g_s2[threadIdx.x], sh2[threadIdx.x]);
    }
}

// ---------------------------------------------------------------- BN1 finalize
__global__ void bn1f_kernel(const float* __restrict__ gamma1,
                            const float* __restrict__ beta1, int n) {
    int d = threadIdx.x;
    if (d < DD) {
        float invn = 1.0f / (float)n;
        float m = g_s1[d] * invn;
        float v = g_s2[d] * invn - m * m;
        float A = gamma1[d] * rsqrtf(v + EPS_BN);
        g_A1[d] = A;
        g_B1[d] = beta1[d] - m * A;
    }
}

// ---------------------------------------------------------------- BN2 stats
__global__ void __launch_bounds__(256) pass2_kernel(
    const float* __restrict__ norm, int n) {
    int total = gridDim.x * blockDim.x;
    int p = threadIdx.x & 31;                    // fixed dim-pair per thread
    float A0 = g_A1[2 * p], A1v = g_A1[2 * p + 1];
    float B0 = g_B1[2 * p], B1v = g_B1[2 * p + 1];
    const float2* ht2 = (const float2*)g_ht;
    float t1a = 0.f, t1b = 0.f, t2a = 0.f, t2b = 0.f;
    int nq = n * 32;
    for (int idx = blockIdx.x * blockDim.x + threadIdx.x; idx < nq; idx += total) {
        int row = idx >> 5;
        float nv = __ldg(&norm[row]);
        float2 h = ht2[idx];
        float y0 = fmaxf(fmaf(h.x, A0, B0) * nv, 0.f);
        float y1 = fmaxf(fmaf(h.y, A1v, B1v) * nv, 0.f);
        t1a += y0; t2a = fmaf(y0, y0, t2a);
        t1b += y1; t2b = fmaf(y1, y1, t2b);
    }
    __shared__ float sh1[DD], sh2[DD];
    if (threadIdx.x < DD) { sh1[threadIdx.x] = 0.f; sh2[threadIdx.x] = 0.f; }
    __syncthreads();
    atomicAdd(&sh1[2 * p], t1a);
    atomicAdd(&sh1[2 * p + 1], t1b);
    atomicAdd(&sh2[2 * p], t2a);
    atomicAdd(&sh2[2 * p + 1], t2b);
    __syncthreads();
    if (threadIdx.x < DD) {
        atomicAdd(&g_t1[threadIdx.x], sh1[threadIdx.x]);
        atomicAdd(&g_t2[threadIdx.x], sh2[threadIdx.x]);
    }
}

// ---------------------------------------------------------------- BN2 finalize
__global__ void bn2f_kernel(const float* __restrict__ gamma2,
                            const float* __restrict__ beta2, int n) {
    int d = threadIdx.x;
    if (d < DD) {
        float invn = 1.0f / (float)n;
        float m = g_t1[d] * invn;
        float v = g_t2[d] * invn - m * m;
        float A = gamma2[d] * rsqrtf(v + EPS_BN);
        g_A2[d] = A;
        g_B2[d] = beta2[d] - m * A;
    }
}

// ---------------------------------------------------------------- final output
__global__ void __launch_bounds__(256) final_kernel(
    const float* __restrict__ norm, float2* __restrict__ out2, int n) {
    int total = gridDim.x * blockDim.x;
    int p = threadIdx.x & 31;
    float A0 = g_A1[2 * p], A1v = g_A1[2 * p + 1];
    float B0 = g_B1[2 * p], B1v = g_B1[2 * p + 1];
    float C0 = g_A2[2 * p], C1 = g_A2[2 * p + 1];
    float D0 = g_B2[2 * p], D1 = g_B2[2 * p + 1];
    const float2* ht2 = (const float2*)g_ht;
    int nq = n * 32;
    for (int idx = blockIdx.x * blockDim.x + threadIdx.x; idx < nq; idx += total) {
        int row = idx >> 5;
        float nv = __ldg(&norm[row]);
        float2 h = ht2[idx];
        float y0 = fmaxf(fmaf(h.x, A0, B0) * nv, 0.f);
        float y1 = fmaxf(fmaf(h.y, A1v, B1v) * nv, 0.f);
        out2[idx] = make_float2(fmaf(y0, C0, D0), fmaf(y1, C1, D1));
    }
}

// ---------------------------------------------------------------------------
extern "C" void kernel_launch(void* const* d_in, const int* in_sizes, int n_in,
                              void* d_out, int out_size) {
    const float* h      = (const float*)d_in[0];
    const float* ef     = (const float*)d_in[1];
    const float* norm   = (const float*)d_in[2];
    const float* gamma1 = (const float*)d_in[3];
    const float* beta1  = (const float*)d_in[4];
    const float* gamma2 = (const float*)d_in[5];
    const float* beta2  = (const float*)d_in[6];
    const int*   src    = (const int*)d_in[7];
    const int*   dst    = (const int*)d_in[8];
    float* out = (float*)d_out;

    int n = in_sizes[2];          // norm has N elements
    int e = in_sizes[7];          // src has E elements
    if (n > N_MAX) n = N_MAX;
    if (e > E_MAX) e = E_MAX;

    const int B = 256;
    const int GRID_PERSIST = 148 * 8;            // ~full chip, grid-stride
    int scan_blocks = (n + SCAN_T - 1) / SCAN_T;

    zero_kernel<<<512, B>>>(n);
    hin_kernel<<<GRID_PERSIST, B>>>((const float4*)h, norm, n);
    deg_kernel<<<2048, B>>>(dst, e);
    scan1_kernel<<<scan_blocks, SCAN_T>>>(n);
    scan2_kernel<<<1, 32>>>(scan_blocks);
    scan3_kernel<<<scan_blocks, SCAN_T>>>(n, e);
    scatter_kernel<<<2048, B>>>(dst, e);
    agg_kernel<<<GRID_PERSIST, B>>>((const float2*)ef, src, n);
    bn1f_kernel<<<1, 64>>>(gamma1, beta1, n);
    pass2_kernel<<<GRID_PERSIST, B>>>(norm, n);
    bn2f_kernel<<<1, 64>>>(gamma2, beta2, n);
    final_kernel<<<GRID_PERSIST, B>>>(norm, (float2*)d_out, n);
}

// round 2
// speedup vs baseline: 1.0568x; 1.0568x over previous
#include <cuda_runtime.h>
#include <math.h>

// ---------------------------------------------------------------------------
// ActivationPNALayer: fused PNA aggregation + tower + 2x BatchNorm
// Inputs (metadata order):
//  0: h      [N*D]  f32
//  1: ef     [E*D]  f32
//  2: norm   [N]    f32
//  3: gamma1 [D]  4: beta1 [D]  5: gamma2 [D]  6: beta2 [D]
//  7: src    [E]  i32
//  8: dst    [E]  i32
// Output: [N*D] f32
// ---------------------------------------------------------------------------

#define N_MAX 100000
#define E_MAX 1600000
#define DD 64
#define AVG_D_LOG 2.8332133440562162f
#define EPS_STD 1e-5f
#define EPS_BN 1e-5f

#define SCAN_T 512
#define SCAN_BMAX 256

// scratch (device globals: allocation-free)
__device__ float g_ht[N_MAX * DD];
__device__ int   g_deg[N_MAX];
__device__ int   g_off[N_MAX + 1];
__device__ int   g_cur[N_MAX];
__device__ int   g_eids[E_MAX];
__device__ int   g_esrc[E_MAX];
__device__ int   g_part[SCAN_BMAX];
__device__ float g_s1[DD], g_s2[DD], g_t1[DD], g_t2[DD];

// ---------------------------------------------------------------- zero scratch
__global__ void zero_kernel(int n) {
    int total = gridDim.x * blockDim.x;
    int i = blockIdx.x * blockDim.x + threadIdx.x;
    for (int k = i; k < n; k += total) g_deg[k] = 0;
    if (i < DD) { g_s1[i] = 0.f; g_s2[i] = 0.f; g_t1[i] = 0.f; g_t2[i] = 0.f; }
}

// ---------------------------------------------------------------- degree count
__global__ void deg_kernel(const int* __restrict__ dst, int e) {
    int total = gridDim.x * blockDim.x;
    for (int i = blockIdx.x * blockDim.x + threadIdx.x; i < e; i += total)
        atomicAdd(&g_deg[dst[i]], 1);
}

// ---------------------------------------------------------------- scan (3 steps)
__global__ void scan1_kernel(int n) {
    __shared__ int sh[SCAN_T];
    int i = blockIdx.x * SCAN_T + threadIdx.x;
    sh[threadIdx.x] = (i < n) ? g_deg[i] : 0;
    __syncthreads();
    for (int s = SCAN_T / 2; s > 0; s >>= 1) {
        if (threadIdx.x < s) sh[threadIdx.x] += sh[threadIdx.x + s];
        __syncthreads();
    }
    if (threadIdx.x == 0) g_part[blockIdx.x] = sh[0];
}

__global__ void scan2_kernel(int nb) {
    __shared__ int sh[SCAN_BMAX];
    int t = threadIdx.x;
    int v = (t < nb) ? g_part[t] : 0;
    sh[t] = v;
    __syncthreads();
    for (int s = 1; s < SCAN_BMAX; s <<= 1) {
        int u = (t >= s) ? sh[t - s] : 0;
        __syncthreads();
        sh[t] += u;
        __syncthreads();
    }
    if (t < nb) g_part[t] = sh[t] - v;   // exclusive
}

__global__ void scan3_kernel(int n, int e_total) {
    __shared__ int sh[SCAN_T];
    int i = blockIdx.x * SCAN_T + threadIdx.x;
    int v = (i < n) ? g_deg[i] : 0;
    sh[threadIdx.x] = v;
    __syncthreads();
    for (int s = 1; s < SCAN_T; s <<= 1) {
        int t = (threadIdx.x >= s) ? sh[threadIdx.x - s] : 0;
        __syncthreads();
        sh[threadIdx.x] += t;
        __syncthreads();
    }
    int excl = sh[threadIdx.x] - v + g_part[blockIdx.x];
    if (i < n) { g_off[i] = excl; g_cur[i] = excl; }
    if (i == 0) g_off[n] = e_total;
}

// ---------------------------------------------------------------- CSR scatter
__global__ void scatter_kernel(const int* __restrict__ dst,
                               const int* __restrict__ src, int e) {
    int total = gridDim.x * blockDim.x;
    for (int i = blockIdx.x * blockDim.x + threadIdx.x; i < e; i += total) {
        int d = dst[i];
        int pos = atomicAdd(&g_cur[d], 1);
        g_eids[pos] = i;
        g_esrc[pos] = src[i];
    }
}

// ---------------------------------------------------------------- aggregation
// one warp per node; lane owns dims (2*lane, 2*lane+1) as float2
__global__ void __launch_bounds__(256) agg_kernel(
    const float2* __restrict__ h2, const float2* __restrict__ ef2,
    const float* __restrict__ norm, int n) {
    const int lane = threadIdx.x & 31;
    const int wpb = blockDim.x >> 5;
    int warpGlobal = blockIdx.x * wpb + (threadIdx.x >> 5);
    int warpStride = gridDim.x * wpb;

    float2* ht2 = (float2*)g_ht;

    float a10 = 0.f, a11 = 0.f, a20 = 0.f, a21 = 0.f;  // BN1 stats accum

    for (int node = warpGlobal; node < n; node += warpStride) {
        int start = g_off[node];
        int end = g_off[node + 1];
        float nvd = __ldg(&norm[node]);
        float2 hd = h2[node * 32 + lane];
        hd.x *= nvd; hd.y *= nvd;                 // h_in for own node

        float s0 = 0.f, s1 = 0.f, q0 = 0.f, q1 = 0.f;
        float mx0 = -INFINITY, mx1 = -INFINITY;
        float mn0 = INFINITY, mn1 = INFINITY;

        for (int base = start; base < end; base += 32) {
            int m = min(32, end - base);
            int e = 0, sv = 0; float nv = 0.f;
            if (lane < m) {
                e = __ldcs(&g_eids[base + lane]);
                sv = __ldcs(&g_esrc[base + lane]);
                nv = __ldg(&norm[sv]);
            }
            #pragma unroll 4
            for (int j = 0; j < m; j++) {
                int ej = __shfl_sync(0xffffffffu, e, j);
                int sj = __shfl_sync(0xffffffffu, sv, j);
                float nj = __shfl_sync(0xffffffffu, nv, j);
                float2 hs = h2[sj * 32 + lane];
                float2 ev = __ldcs(&ef2[ej * 32 + lane]);
                float z0 = fmaf(hs.x, nj, hd.x + ev.x);
                float z1 = fmaf(hs.y, nj, hd.y + ev.y);
                s0 += z0; q0 = fmaf(z0, z0, q0);
                mx0 = fmaxf(mx0, z0); mn0 = fminf(mn0, z0);
                s1 += z1; q1 = fmaf(z1, z1, q1);
                mx1 = fmaxf(mx1, z1); mn1 = fminf(mn1, z1);
            }
        }

        float fdeg = (float)(end - start);
        float inv = 1.0f / fdeg;
        float mean0 = s0 * inv, mean1 = s1 * inv;
        float var0 = fmaxf(q0 * inv - mean0 * mean0, 0.f);
        float var1 = fmaxf(q1 * inv - mean1 * mean1, 0.f);
        float std0 = sqrtf(var0 + EPS_STD);
        float std1 = sqrtf(var1 + EPS_STD);
        float logd = logf(fdeg + 1.0f);
        float c = 1.0f + logd * (1.0f / AVG_D_LOG) + AVG_D_LOG / logd;
        float p0 = (hd.x + (mean0 + mx0 + mn0 + std0) * c) * (1.0f / 13.0f);
        float p1 = (hd.y + (mean1 + mx1 + mn1 + std1) * c) * (1.0f / 13.0f);
        ht2[node * 32 + lane] = make_float2(p0, p1);

        a10 += p0; a11 += p1;
        a20 = fmaf(p0, p0, a20); a21 = fmaf(p1, p1, a21);
    }

    // hierarchical BN1-stat reduction: regs -> shared -> global atomics
    __shared__ float sh1[DD], sh2[DD];
    if (threadIdx.x < DD) { sh1[threadIdx.x] = 0.f; sh2[threadIdx.x] = 0.f; }
    __syncthreads();
    atomicAdd(&sh1[2 * lane], a10);
    atomicAdd(&sh1[2 * lane + 1], a11);
    atomicAdd(&sh2[2 * lane], a20);
    atomicAdd(&sh2[2 * lane + 1], a21);
    __syncthreads();
    if (threadIdx.x < DD) {
        atomicAdd(&g_s1[threadIdx.x], sh1[threadIdx.x]);
        atomicAdd(&g_s2[threadIdx.x], sh2[threadIdx.x]);
    }
}

// ---------------------------------------------------------------- BN2 stats
// (BN1 affine recomputed per thread from g_s1/g_s2 — 64 floats, L2-hot)
__global__ void __launch_bounds__(256) pass2_kernel(
    const float* __restrict__ norm, const float* __restrict__ gamma1,
    const float* __restrict__ beta1, int n) {
    int total = gridDim.x * blockDim.x;
    int p = threadIdx.x & 31;                    // fixed dim-pair per thread
    float invn = 1.0f / (float)n;
    float m0 = g_s1[2 * p] * invn, m1 = g_s1[2 * p + 1] * invn;
    float v0 = g_s2[2 * p] * invn - m0 * m0;
    float v1 = g_s2[2 * p + 1] * invn - m1 * m1;
    float A0 = __ldg(&gamma1[2 * p]) * rsqrtf(v0 + EPS_BN);
    float A1v = __ldg(&gamma1[2 * p + 1]) * rsqrtf(v1 + EPS_BN);
    float B0 = __ldg(&beta1[2 * p]) - m0 * A0;
    float B1v = __ldg(&beta1[2 * p + 1]) - m1 * A1v;

    const float2* ht2 = (const float2*)g_ht;
    float t1a = 0.f, t1b = 0.f, t2a = 0.f, t2b = 0.f;
    int nq = n * 32;
    for (int idx = blockIdx.x * blockDim.x + threadIdx.x; idx < nq; idx += total) {
        int row = idx >> 5;
        float nv = __ldg(&norm[row]);
        float2 h = ht2[idx];
        float y0 = fmaxf(fmaf(h.x, A0, B0) * nv, 0.f);
        float y1 = fmaxf(fmaf(h.y, A1v, B1v) * nv, 0.f);
        t1a += y0; t2a = fmaf(y0, y0, t2a);
        t1b += y1; t2b = fmaf(y1, y1, t2b);
    }
    __shared__ float sh1[DD], sh2[DD];
    if (threadIdx.x < DD) { sh1[threadIdx.x] = 0.f; sh2[threadIdx.x] = 0.f; }
    __syncthreads();
    atomicAdd(&sh1[2 * p], t1a);
    atomicAdd(&sh1[2 * p + 1], t1b);
    atomicAdd(&sh2[2 * p], t2a);
    atomicAdd(&sh2[2 * p + 1], t2b);
    __syncthreads();
    if (threadIdx.x < DD) {
        atomicAdd(&g_t1[threadIdx.x], sh1[threadIdx.x]);
        atomicAdd(&g_t2[threadIdx.x], sh2[threadIdx.x]);
    }
}

// ---------------------------------------------------------------- final output
__global__ void __launch_bounds__(256) final_kernel(
    const float* __restrict__ norm, const float* __restrict__ gamma1,
    const float* __restrict__ beta1, const float* __restrict__ gamma2,
    const float* __restrict__ beta2, float2* __restrict__ out2, int n) {
    int total = gridDim.x * blockDim.x;
    int p = threadIdx.x & 31;
    float invn = 1.0f / (float)n;
    float m0 = g_s1[2 * p] * invn, m1 = g_s1[2 * p + 1] * invn;
    float v0 = g_s2[2 * p] * invn - m0 * m0;
    float v1 = g_s2[2 * p + 1] * invn - m1 * m1;
    float A0 = __ldg(&gamma1[2 * p]) * rsqrtf(v0 + EPS_BN);
    float A1v = __ldg(&gamma1[2 * p + 1]) * rsqrtf(v1 + EPS_BN);
    float B0 = __ldg(&beta1[2 * p]) - m0 * A0;
    float B1v = __ldg(&beta1[2 * p + 1]) - m1 * A1v;

    float n0 = g_t1[2 * p] * invn, n1 = g_t1[2 * p + 1] * invn;
    float w0 = g_t2[2 * p] * invn - n0 * n0;
    float w1 = g_t2[2 * p + 1] * invn - n1 * n1;
    float C0 = __ldg(&gamma2[2 * p]) * rsqrtf(w0 + EPS_BN);
    float C1 = __ldg(&gamma2[2 * p + 1]) * rsqrtf(w1 + EPS_BN);
    float D0 = __ldg(&beta2[2 * p]) - n0 * C0;
    float D1 = __ldg(&beta2[2 * p + 1]) - n1 * C1;

    const float2* ht2 = (const float2*)g_ht;
    int nq = n * 32;
    for (int idx = blockIdx.x * blockDim.x + threadIdx.x; idx < nq; idx += total) {
        int row = idx >> 5;
        float nv = __ldg(&norm[row]);
        float2 h = ht2[idx];
        float y0 = fmaxf(fmaf(h.x, A0, B0) * nv, 0.f);
        float y1 = fmaxf(fmaf(h.y, A1v, B1v) * nv, 0.f);
        out2[idx] = make_float2(fmaf(y0, C0, D0), fmaf(y1, C1, D1));
    }
}

// ---------------------------------------------------------------------------
extern "C" void kernel_launch(void* const* d_in, const int* in_sizes, int n_in,
                              void* d_out, int out_size) {
    const float* h      = (const float*)d_in[0];
    const float* ef     = (const float*)d_in[1];
    const float* norm   = (const float*)d_in[2];
    const float* gamma1 = (const float*)d_in[3];
    const float* beta1  = (const float*)d_in[4];
    const float* gamma2 = (const float*)d_in[5];
    const float* beta2  = (const float*)d_in[6];
    const int*   src    = (const int*)d_in[7];
    const int*   dst    = (const int*)d_in[8];

    int n = in_sizes[2];          // norm has N elements
    int e = in_sizes[7];          // src has E elements
    if (n > N_MAX) n = N_MAX;
    if (e > E_MAX) e = E_MAX;

    const int B = 256;
    const int GRID_PERSIST = 148 * 8;
    int scan_blocks = (n + SCAN_T - 1) / SCAN_T;

    zero_kernel<<<512, B>>>(n);
    deg_kernel<<<2048, B>>>(dst, e);
    scan1_kernel<<<scan_blocks, SCAN_T>>>(n);
    scan2_kernel<<<1, SCAN_BMAX>>>(scan_blocks);
    scan3_kernel<<<scan_blocks, SCAN_T>>>(n, e);
    scatter_kernel<<<2048, B>>>(dst, src, e);
    agg_kernel<<<GRID_PERSIST, B>>>((const float2*)h, (const float2*)ef, norm, n);
    pass2_kernel<<<GRID_PERSIST, B>>>(norm, gamma1, beta1, n);
    final_kernel<<<GRID_PERSIST, B>>>(norm, gamma1, beta1, gamma2, beta2,
                                      (float2*)d_out, n);
}

// round 3
// speedup vs baseline: 1.0640x; 1.0069x over previous
#include <cuda_runtime.h>
#include <math.h>

// ---------------------------------------------------------------------------
// ActivationPNALayer: fused PNA aggregation + tower + 2x BatchNorm
// Inputs (metadata order):
//  0: h      [N*D]  f32
//  1: ef     [E*D]  f32
//  2: norm   [N]    f32
//  3: gamma1 [D]  4: beta1 [D]  5: gamma2 [D]  6: beta2 [D]
//  7: src    [E]  i32
//  8: dst    [E]  i32
// Output: [N*D] f32
// ---------------------------------------------------------------------------

#define N_MAX 100000
#define E_MAX 1600000
#define DD 64
#define AVG_D_LOG 2.8332133440562162f
#define EPS_STD 1e-5f
#define EPS_BN 1e-5f

#define SCAN_T 512
#define SCAN_BMAX 256

// scratch (device globals: allocation-free)
__device__ float g_ht[N_MAX * DD];
__device__ int   g_deg[N_MAX];
__device__ int   g_off[N_MAX + 1];
__device__ int   g_cur[N_MAX];
__device__ int   g_eids[E_MAX];
__device__ int   g_esrc[E_MAX];
__device__ int   g_part[SCAN_BMAX];
__device__ float g_s1[DD], g_s2[DD], g_t1[DD], g_t2[DD];

// ---------------------------------------------------------------- zero scratch
__global__ void zero_kernel(int n) {
    int total = gridDim.x * blockDim.x;
    int i = blockIdx.x * blockDim.x + threadIdx.x;
    for (int k = i; k < n; k += total) g_deg[k] = 0;
    if (i < DD) { g_s1[i] = 0.f; g_s2[i] = 0.f; g_t1[i] = 0.f; g_t2[i] = 0.f; }
}

// ---------------------------------------------------------------- degree count
__global__ void deg_kernel(const int* __restrict__ dst, int e) {
    int total = gridDim.x * blockDim.x;
    for (int i = blockIdx.x * blockDim.x + threadIdx.x; i < e; i += total)
        atomicAdd(&g_deg[dst[i]], 1);
}

// ---------------------------------------------------------------- scan (3 steps)
__global__ void scan1_kernel(int n) {
    __shared__ int sh[SCAN_T];
    int i = blockIdx.x * SCAN_T + threadIdx.x;
    sh[threadIdx.x] = (i < n) ? g_deg[i] : 0;
    __syncthreads();
    for (int s = SCAN_T / 2; s > 0; s >>= 1) {
        if (threadIdx.x < s) sh[threadIdx.x] += sh[threadIdx.x + s];
        __syncthreads();
    }
    if (threadIdx.x == 0) g_part[blockIdx.x] = sh[0];
}

__global__ void scan2_kernel(int nb) {
    __shared__ int sh[SCAN_BMAX];
    int t = threadIdx.x;
    int v = (t < nb) ? g_part[t] : 0;
    sh[t] = v;
    __syncthreads();
    for (int s = 1; s < SCAN_BMAX; s <<= 1) {
        int u = (t >= s) ? sh[t - s] : 0;
        __syncthreads();
        sh[t] += u;
        __syncthreads();
    }
    if (t < nb) g_part[t] = sh[t] - v;   // exclusive
}

__global__ void scan3_kernel(int n, int e_total) {
    __shared__ int sh[SCAN_T];
    int i = blockIdx.x * SCAN_T + threadIdx.x;
    int v = (i < n) ? g_deg[i] : 0;
    sh[threadIdx.x] = v;
    __syncthreads();
    for (int s = 1; s < SCAN_T; s <<= 1) {
        int t = (threadIdx.x >= s) ? sh[threadIdx.x - s] : 0;
        __syncthreads();
        sh[threadIdx.x] += t;
        __syncthreads();
    }
    int excl = sh[threadIdx.x] - v + g_part[blockIdx.x];
    if (i < n) { g_off[i] = excl; g_cur[i] = excl; }
    if (i == 0) g_off[n] = e_total;
}

// ---------------------------------------------------------------- CSR scatter
__global__ void scatter_kernel(const int* __restrict__ dst,
                               const int* __restrict__ src, int e) {
    int total = gridDim.x * blockDim.x;
    for (int i = blockIdx.x * blockDim.x + threadIdx.x; i < e; i += total) {
        int d = dst[i];
        int pos = atomicAdd(&g_cur[d], 1);
        g_eids[pos] = i;
        g_esrc[pos] = src[i];
    }
}

// ---------------------------------------------------------------- aggregation
// one warp per node; lane owns dims (2*lane, 2*lane+1) as float2
__global__ void __launch_bounds__(256) agg_kernel(
    const float2* __restrict__ h2, const float2* __restrict__ ef2,
    const float* __restrict__ norm, int n) {
    const int lane = threadIdx.x & 31;
    const int wpb = blockDim.x >> 5;
    int warpGlobal = blockIdx.x * wpb + (threadIdx.x >> 5);
    int warpStride = gridDim.x * wpb;

    float2* ht2 = (float2*)g_ht;

    float a10 = 0.f, a11 = 0.f, a20 = 0.f, a21 = 0.f;  // BN1 stats accum

    for (int node = warpGlobal; node < n; node += warpStride) {
        int start = g_off[node];
        int end = g_off[node + 1];
        float nvd = __ldg(&norm[node]);
        float2 hd = h2[node * 32 + lane];
        hd.x *= nvd; hd.y *= nvd;                 // h_in for own node

        float s0 = 0.f, s1 = 0.f, q0 = 0.f, q1 = 0.f;
        float mx0 = -INFINITY, mx1 = -INFINITY;
        float mn0 = INFINITY, mn1 = INFINITY;

        for (int base = start; base < end; base += 32) {
            int m = min(32, end - base);
            int e = 0, sv = 0; float nv = 0.f;
            if (lane < m) {
                e = __ldcs(&g_eids[base + lane]);
                sv = __ldcs(&g_esrc[base + lane]);
                nv = __ldg(&norm[sv]);
            }
            #pragma unroll 4
            for (int j = 0; j < m; j++) {
                int ej = __shfl_sync(0xffffffffu, e, j);
                int sj = __shfl_sync(0xffffffffu, sv, j);
                float nj = __shfl_sync(0xffffffffu, nv, j);
                float2 hs = h2[sj * 32 + lane];
                float2 ev = __ldcs(&ef2[ej * 32 + lane]);
                float z0 = fmaf(hs.x, nj, hd.x + ev.x);
                float z1 = fmaf(hs.y, nj, hd.y + ev.y);
                s0 += z0; q0 = fmaf(z0, z0, q0);
                mx0 = fmaxf(mx0, z0); mn0 = fminf(mn0, z0);
                s1 += z1; q1 = fmaf(z1, z1, q1);
                mx1 = fmaxf(mx1, z1); mn1 = fminf(mn1, z1);
            }
        }

        float fdeg = (float)(end - start);
        float inv = 1.0f / fdeg;
        float mean0 = s0 * inv, mean1 = s1 * inv;
        float var0 = fmaxf(q0 * inv - mean0 * mean0, 0.f);
        float var1 = fmaxf(q1 * inv - mean1 * mean1, 0.f);
        float std0 = sqrtf(var0 + EPS_STD);
        float std1 = sqrtf(var1 + EPS_STD);
        float logd = logf(fdeg + 1.0f);
        float c = 1.0f + logd * (1.0f / AVG_D_LOG) + AVG_D_LOG / logd;
        float p0 = (hd.x + (mean0 + mx0 + mn0 + std0) * c) * (1.0f / 13.0f);
        float p1 = (hd.y + (mean1 + mx1 + mn1 + std1) * c) * (1.0f / 13.0f);
        ht2[node * 32 + lane] = make_float2(p0, p1);

        a10 += p0; a11 += p1;
        a20 = fmaf(p0, p0, a20); a21 = fmaf(p1, p1, a21);
    }

    // hierarchical BN1-stat reduction: regs -> shared -> global atomics
    __shared__ float sh1[DD], sh2[DD];
    if (threadIdx.x < DD) { sh1[threadIdx.x] = 0.f; sh2[threadIdx.x] = 0.f; }
    __syncthreads();
    atomicAdd(&sh1[2 * lane], a10);
    atomicAdd(&sh1[2 * lane + 1], a11);
    atomicAdd(&sh2[2 * lane], a20);
    atomicAdd(&sh2[2 * lane + 1], a21);
    __syncthreads();
    if (threadIdx.x < DD) {
        atomicAdd(&g_s1[threadIdx.x], sh1[threadIdx.x]);
        atomicAdd(&g_s2[threadIdx.x], sh2[threadIdx.x]);
    }
}

// ---------------------------------------------------------------- BN2 stats
// (BN1 affine recomputed per thread from g_s1/g_s2 — 64 floats, L2-hot)
__global__ void __launch_bounds__(256) pass2_kernel(
    const float* __restrict__ norm, const float* __restrict__ gamma1,
    const float* __restrict__ beta1, int n) {
    int total = gridDim.x * blockDim.x;
    int p = threadIdx.x & 31;                    // fixed dim-pair per thread
    float invn = 1.0f / (float)n;
    float m0 = g_s1[2 * p] * invn, m1 = g_s1[2 * p + 1] * invn;
    float v0 = g_s2[2 * p] * invn - m0 * m0;
    float v1 = g_s2[2 * p + 1] * invn - m1 * m1;
    float A0 = __ldg(&gamma1[2 * p]) * rsqrtf(v0 + EPS_BN);
    float A1v = __ldg(&gamma1[2 * p + 1]) * rsqrtf(v1 + EPS_BN);
    float B0 = __ldg(&beta1[2 * p]) - m0 * A0;
    float B1v = __ldg(&beta1[2 * p + 1]) - m1 * A1v;

    const float2* ht2 = (const float2*)g_ht;
    float t1a = 0.f, t1b = 0.f, t2a = 0.f, t2b = 0.f;
    int nq = n * 32;
    for (int idx = blockIdx.x * blockDim.x + threadIdx.x; idx < nq; idx += total) {
        int row = idx >> 5;
        float nv = __ldg(&norm[row]);
        float2 h = ht2[idx];
        float y0 = fmaxf(fmaf(h.x, A0, B0) * nv, 0.f);
        float y1 = fmaxf(fmaf(h.y, A1v, B1v) * nv, 0.f);
        t1a += y0; t2a = fmaf(y0, y0, t2a);
        t1b += y1; t2b = fmaf(y1, y1, t2b);
    }
    __shared__ float sh1[DD], sh2[DD];
    if (threadIdx.x < DD) { sh1[threadIdx.x] = 0.f; sh2[threadIdx.x] = 0.f; }
    __syncthreads();
    atomicAdd(&sh1[2 * p], t1a);
    atomicAdd(&sh1[2 * p + 1], t1b);
    atomicAdd(&sh2[2 * p], t2a);
    atomicAdd(&sh2[2 * p + 1], t2b);
    __syncthreads();
    if (threadIdx.x < DD) {
        atomicAdd(&g_t1[threadIdx.x], sh1[threadIdx.x]);
        atomicAdd(&g_t2[threadIdx.x], sh2[threadIdx.x]);
    }
}

// ---------------------------------------------------------------- final output
__global__ void __launch_bounds__(256) final_kernel(
    const float* __restrict__ norm, const float* __restrict__ gamma1,
    const float* __restrict__ beta1, const float* __restrict__ gamma2,
    const float* __restrict__ beta2, float2* __restrict__ out2, int n) {
    int total = gridDim.x * blockDim.x;
    int p = threadIdx.x & 31;
    float invn = 1.0f / (float)n;
    float m0 = g_s1[2 * p] * invn, m1 = g_s1[2 * p + 1] * invn;
    float v0 = g_s2[2 * p] * invn - m0 * m0;
    float v1 = g_s2[2 * p + 1] * invn - m1 * m1;
    float A0 = __ldg(&gamma1[2 * p]) * rsqrtf(v0 + EPS_BN);
    float A1v = __ldg(&gamma1[2 * p + 1]) * rsqrtf(v1 + EPS_BN);
    float B0 = __ldg(&beta1[2 * p]) - m0 * A0;
    float B1v = __ldg(&beta1[2 * p + 1]) - m1 * A1v;

    float n0 = g_t1[2 * p] * invn, n1 = g_t1[2 * p + 1] * invn;
    float w0 = g_t2[2 * p] * invn - n0 * n0;
    float w1 = g_t2[2 * p + 1] * invn - n1 * n1;
    float C0 = __ldg(&gamma2[2 * p]) * rsqrtf(w0 + EPS_BN);
    float C1 = __ldg(&gamma2[2 * p + 1]) * rsqrtf(w1 + EPS_BN);
    float D0 = __ldg(&beta2[2 * p]) - n0 * C0;
    float D1 = __ldg(&beta2[2 * p + 1]) - n1 * C1;

    const float2* ht2 = (const float2*)g_ht;
    int nq = n * 32;
    for (int idx = blockIdx.x * blockDim.x + threadIdx.x; idx < nq; idx += total) {
        int row = idx >> 5;
        float nv = __ldg(&norm[row]);
        float2 h = ht2[idx];
        float y0 = fmaxf(fmaf(h.x, A0, B0) * nv, 0.f);
        float y1 = fmaxf(fmaf(h.y, A1v, B1v) * nv, 0.f);
        out2[idx] = make_float2(fmaf(y0, C0, D0), fmaf(y1, C1, D1));
    }
}

// ---------------------------------------------------------------------------
extern "C" void kernel_launch(void* const* d_in, const int* in_sizes, int n_in,
                              void* d_out, int out_size) {
    const float* h      = (const float*)d_in[0];
    const float* ef     = (const float*)d_in[1];
    const float* norm   = (const float*)d_in[2];
    const float* gamma1 = (const float*)d_in[3];
    const float* beta1  = (const float*)d_in[4];
    const float* gamma2 = (const float*)d_in[5];
    const float* beta2  = (const float*)d_in[6];
    const int*   src    = (const int*)d_in[7];
    const int*   dst    = (const int*)d_in[8];

    int n = in_sizes[2];          // norm has N elements
    int e = in_sizes[7];          // src has E elements
    if (n > N_MAX) n = N_MAX;
    if (e > E_MAX) e = E_MAX;

    const int B = 256;
    const int GRID_PERSIST = 148 * 8;
    int scan_blocks = (n + SCAN_T - 1) / SCAN_T;

    zero_kernel<<<512, B>>>(n);
    deg_kernel<<<2048, B>>>(dst, e);
    scan1_kernel<<<scan_blocks, SCAN_T>>>(n);
    scan2_kernel<<<1, SCAN_BMAX>>>(scan_blocks);
    scan3_kernel<<<scan_blocks, SCAN_T>>>(n, e);
    scatter_kernel<<<2048, B>>>(dst, src, e);
    agg_kernel<<<GRID_PERSIST, B>>>((const float2*)h, (const float2*)ef, norm, n);
    pass2_kernel<<<GRID_PERSIST, B>>>(norm, gamma1, beta1, n);
    final_kernel<<<GRID_PERSIST, B>>>(norm, gamma1, beta1, gamma2, beta2,
                                      (float2*)d_out, n);
}

// round 4
// speedup vs baseline: 1.2339x; 1.1597x over previous
#include <cuda_runtime.h>
#include <math.h>

// ---------------------------------------------------------------------------
// ActivationPNALayer: fused PNA aggregation + tower + 2x BatchNorm
// Inputs (metadata order):
//  0: h [N*D] f32   1: ef [E*D] f32   2: norm [N] f32
//  3: gamma1 [D]    4: beta1 [D]      5: gamma2 [D]    6: beta2 [D]
//  7: src [E] i32   8: dst [E] i32
// Output: [N*D] f32
// ---------------------------------------------------------------------------

#define N_MAX 100000
#define E_MAX 1600000
#define DD 64
#define AVG_D_LOG 2.8332133440562162f
#define EPS_STD 1e-5f
#define EPS_BN 1e-5f

#define SCAN_T 512
#define SCAN_BMAX 256

// scratch (device globals: allocation-free)
__device__ float g_hin[N_MAX * DD];
__device__ float g_ht[N_MAX * DD];
__device__ int   g_deg[N_MAX];
__device__ int   g_off[N_MAX + 1];
__device__ int   g_cur[N_MAX];
__device__ int2  g_epack[E_MAX];                  // {eid, src} per CSR slot
__device__ unsigned long long g_scan_state[SCAN_BMAX];
__device__ float g_s1[DD], g_s2[DD], g_t1[DD], g_t2[DD];

// ------------------------------------------------- degree count + h_in = h*norm
__global__ void __launch_bounds__(256) deg_hin_kernel(
    const int* __restrict__ dst, const float4* __restrict__ h4,
    const float* __restrict__ norm, int n, int e) {
    int total = gridDim.x * blockDim.x;
    int tid = blockIdx.x * blockDim.x + threadIdx.x;
    for (int i = tid; i < e; i += total)
        atomicAdd(&g_deg[dst[i]], 1);
    int nq = n * (DD / 4);
    float4* o4 = (float4*)g_hin;
    for (int i = tid; i < nq; i += total) {
        int row = i >> 4;
        float nv = __ldg(&norm[row]);
        float4 v = h4[i];
        v.x *= nv; v.y *= nv; v.z *= nv; v.w *= nv;
        o4[i] = v;
    }
}

// ------------------------------------------------- single-pass scan (lookback)
// g_scan_state[b]: flag in high 32 bits (0=invalid, 1=partial, 2=inclusive),
// value in low 32 bits. Must be memset to 0 before launch.
__global__ void __launch_bounds__(SCAN_T) scan_kernel(int n, int e_total) {
    __shared__ int sh[SCAN_T];
    __shared__ int sh_prefix;
    int bid = blockIdx.x, tid = threadIdx.x;
    int i = bid * SCAN_T + tid;
    int v = (i < n) ? g_deg[i] : 0;
    sh[tid] = v;
    __syncthreads();
    for (int s = 1; s < SCAN_T; s <<= 1) {
        int t = (tid >= s) ? sh[tid - s] : 0;
        __syncthreads();
        sh[tid] += t;
        __syncthreads();
    }
    int total = sh[SCAN_T - 1];

    if (tid == 0) {
        if (bid == 0) {
            sh_prefix = 0;
            atomicExch(&g_scan_state[0], (2ULL << 32) | (unsigned)total);
        } else {
            atomicExch(&g_scan_state[bid], (1ULL << 32) | (unsigned)total);
            unsigned long long prefix = 0;
            int j = bid - 1;
            while (true) {
                unsigned long long s = atomicAdd(&g_scan_state[j], 0ULL);
                unsigned f = (unsigned)(s >> 32);
                if (f == 2u) { prefix += (unsigned)s; break; }
                if (f == 1u) { prefix += (unsigned)s; j--; }
            }
            atomicExch(&g_scan_state[bid],
                       (2ULL << 32) | (unsigned)(prefix + (unsigned)total));
            sh_prefix = (int)prefix;
        }
    }
    // zero BN stat accumulators (before agg/pass2 consume them)
    if (bid == 0) {
        if (tid < DD) g_s1[tid] = 0.f;
        else if (tid < 2 * DD) g_s2[tid - DD] = 0.f;
        else if (tid < 3 * DD) g_t1[tid - 2 * DD] = 0.f;
        else if (tid < 4 * DD) g_t2[tid - 3 * DD] = 0.f;
    }
    __syncthreads();
    int excl = sh_prefix + sh[tid] - v;
    if (i < n) { g_off[i] = excl; g_cur[i] = excl; }
    if (i == 0) g_off[n] = e_total;
}

// ------------------------------------------------- CSR scatter (packed records)
__global__ void __launch_bounds__(256) scatter_kernel(
    const int* __restrict__ dst, const int* __restrict__ src, int e) {
    int total = gridDim.x * blockDim.x;
    for (int i = blockIdx.x * blockDim.x + threadIdx.x; i < e; i += total) {
        int d = dst[i];
        int pos = atomicAdd(&g_cur[d], 1);
        g_epack[pos] = make_int2(i, src[i]);
    }
}

// ------------------------------------------------- aggregation
// one warp per node; lane owns dims (2*lane, 2*lane+1) as float2
// edge records staged through shared memory, broadcast via LDS
__global__ void __launch_bounds__(256) agg_kernel(const float2* __restrict__ ef2,
                                                  int n) {
    __shared__ int2 srec[8][32];
    const int lane = threadIdx.x & 31;
    const int w = threadIdx.x >> 5;
    const int wpb = blockDim.x >> 5;
    int warpGlobal = blockIdx.x * wpb + w;
    int warpStride = gridDim.x * wpb;

    const float2* hin2 = (const float2*)g_hin;
    float2* ht2 = (float2*)g_ht;

    float a10 = 0.f, a11 = 0.f, a20 = 0.f, a21 = 0.f;   // BN1 stats accum

    for (int node = warpGlobal; node < n; node += warpStride) {
        int start = g_off[node];
        int end = g_off[node + 1];
        float2 hd = hin2[node * 32 + lane];

        float s0 = 0.f, s1 = 0.f, q0 = 0.f, q1 = 0.f;
        float mx0 = -INFINITY, mx1 = -INFINITY;
        float mn0 = INFINITY, mn1 = INFINITY;

        for (int base = start; base < end; base += 32) {
            int m = min(32, end - base);
            if (lane < m) srec[w][lane] = __ldcs(&g_epack[base + lane]);
            __syncwarp();
            #pragma unroll 4
            for (int j = 0; j < m; j++) {
                int2 r = srec[w][j];                     // LDS.64 broadcast
                float2 hs = hin2[r.y * 32 + lane];
                float2 ev = __ldcs(&ef2[r.x * 32 + lane]);
                float z0 = hd.x + hs.x + ev.x;
                float z1 = hd.y + hs.y + ev.y;
                s0 += z0; q0 = fmaf(z0, z0, q0);
                mx0 = fmaxf(mx0, z0); mn0 = fminf(mn0, z0);
                s1 += z1; q1 = fmaf(z1, z1, q1);
                mx1 = fmaxf(mx1, z1); mn1 = fminf(mn1, z1);
            }
            __syncwarp();
        }

        float fdeg = (float)(end - start);
        float inv = 1.0f / fdeg;
        float mean0 = s0 * inv, mean1 = s1 * inv;
        float var0 = fmaxf(q0 * inv - mean0 * mean0, 0.f);
        float var1 = fmaxf(q1 * inv - mean1 * mean1, 0.f);
        float std0 = sqrtf(var0 + EPS_STD);
        float std1 = sqrtf(var1 + EPS_STD);
        float logd = logf(fdeg + 1.0f);
        float c = 1.0f + logd * (1.0f / AVG_D_LOG) + AVG_D_LOG / logd;
        float p0 = (hd.x + (mean0 + mx0 + mn0 + std0) * c) * (1.0f / 13.0f);
        float p1 = (hd.y + (mean1 + mx1 + mn1 + std1) * c) * (1.0f / 13.0f);
        ht2[node * 32 + lane] = make_float2(p0, p1);

        a10 += p0; a11 += p1;
        a20 = fmaf(p0, p0, a20); a21 = fmaf(p1, p1, a21);
    }

    // hierarchical BN1-stat reduction: regs -> shared -> global atomics
    __shared__ float sh1[DD], sh2[DD];
    if (threadIdx.x < DD) { sh1[threadIdx.x] = 0.f; sh2[threadIdx.x] = 0.f; }
    __syncthreads();
    atomicAdd(&sh1[2 * lane], a10);
    atomicAdd(&sh1[2 * lane + 1], a11);
    atomicAdd(&sh2[2 * lane], a20);
    atomicAdd(&sh2[2 * lane + 1], a21);
    __syncthreads();
    if (threadIdx.x < DD) {
        atomicAdd(&g_s1[threadIdx.x], sh1[threadIdx.x]);
        atomicAdd(&g_s2[threadIdx.x], sh2[threadIdx.x]);
    }
}

// ------------------------------------------------- BN2 stats
__global__ void __launch_bounds__(256) pass2_kernel(
    const float* __restrict__ norm, const float* __restrict__ gamma1,
    const float* __restrict__ beta1, int n) {
    int total = gridDim.x * blockDim.x;
    int p = threadIdx.x & 31;
    float invn = 1.0f / (float)n;
    float m0 = g_s1[2 * p] * invn, m1 = g_s1[2 * p + 1] * invn;
    float v0 = g_s2[2 * p] * invn - m0 * m0;
    float v1 = g_s2[2 * p + 1] * invn - m1 * m1;
    float A0 = __ldg(&gamma1[2 * p]) * rsqrtf(v0 + EPS_BN);
    float A1v = __ldg(&gamma1[2 * p + 1]) * rsqrtf(v1 + EPS_BN);
    float B0 = __ldg(&beta1[2 * p]) - m0 * A0;
    float B1v = __ldg(&beta1[2 * p + 1]) - m1 * A1v;

    const float2* ht2 = (const float2*)g_ht;
    float t1a = 0.f, t1b = 0.f, t2a = 0.f, t2b = 0.f;
    int nq = n * 32;
    for (int idx = blockIdx.x * blockDim.x + threadIdx.x; idx < nq; idx += total) {
        int row = idx >> 5;
        float nv = __ldg(&norm[row]);
        float2 h = ht2[idx];
        float y0 = fmaxf(fmaf(h.x, A0, B0) * nv, 0.f);
        float y1 = fmaxf(fmaf(h.y, A1v, B1v) * nv, 0.f);
        t1a += y0; t2a = fmaf(y0, y0, t2a);
        t1b += y1; t2b = fmaf(y1, y1, t2b);
    }
    __shared__ float sh1[DD], sh2[DD];
    if (threadIdx.x < DD) { sh1[threadIdx.x] = 0.f; sh2[threadIdx.x] = 0.f; }
    __syncthreads();
    atomicAdd(&sh1[2 * p], t1a);
    atomicAdd(&sh1[2 * p + 1], t1b);
    atomicAdd(&sh2[2 * p], t2a);
    atomicAdd(&sh2[2 * p + 1], t2b);
    __syncthreads();
    if (threadIdx.x < DD) {
        atomicAdd(&g_t1[threadIdx.x], sh1[threadIdx.x]);
        atomicAdd(&g_t2[threadIdx.x], sh2[threadIdx.x]);
    }
}

// ------------------------------------------------- final output
__global__ void __launch_bounds__(256) final_kernel(
    const float* __restrict__ norm, const float* __restrict__ gamma1,
    const float* __restrict__ beta1, const float* __restrict__ gamma2,
    const float* __restrict__ beta2, float2* __restrict__ out2, int n) {
    int total = gridDim.x * blockDim.x;
    int p = threadIdx.x & 31;
    float invn = 1.0f / (float)n;
    float m0 = g_s1[2 * p] * invn, m1 = g_s1[2 * p + 1] * invn;
    float v0 = g_s2[2 * p] * invn - m0 * m0;
    float v1 = g_s2[2 * p + 1] * invn - m1 * m1;
    float A0 = __ldg(&gamma1[2 * p]) * rsqrtf(v0 + EPS_BN);
    float A1v = __ldg(&gamma1[2 * p + 1]) * rsqrtf(v1 + EPS_BN);
    float B0 = __ldg(&beta1[2 * p]) - m0 * A0;
    float B1v = __ldg(&beta1[2 * p + 1]) - m1 * A1v;

    float n0 = g_t1[2 * p] * invn, n1 = g_t1[2 * p + 1] * invn;
    float w0 = g_t2[2 * p] * invn - n0 * n0;
    float w1 = g_t2[2 * p + 1] * invn - n1 * n1;
    float C0 = __ldg(&gamma2[2 * p]) * rsqrtf(w0 + EPS_BN);
    float C1 = __ldg(&gamma2[2 * p + 1]) * rsqrtf(w1 + EPS_BN);
    float D0 = __ldg(&beta2[2 * p]) - n0 * C0;
    float D1 = __ldg(&beta2[2 * p + 1]) - n1 * C1;

    const float2* ht2 = (const float2*)g_ht;
    int nq = n * 32;
    for (int idx = blockIdx.x * blockDim.x + threadIdx.x; idx < nq; idx += total) {
        int row = idx >> 5;
        float nv = __ldg(&norm[row]);
        float2 h = ht2[idx];
        float y0 = fmaxf(fmaf(h.x, A0, B0) * nv, 0.f);
        float y1 = fmaxf(fmaf(h.y, A1v, B1v) * nv, 0.f);
        out2[idx] = make_float2(fmaf(y0, C0, D0), fmaf(y1, C1, D1));
    }
}

// ---------------------------------------------------------------------------
extern "C" void kernel_launch(void* const* d_in, const int* in_sizes, int n_in,
                              void* d_out, int out_size) {
    const float* h      = (const float*)d_in[0];
    const float* ef     = (const float*)d_in[1];
    const float* norm   = (const float*)d_in[2];
    const float* gamma1 = (const float*)d_in[3];
    const float* beta1  = (const float*)d_in[4];
    const float* gamma2 = (const float*)d_in[5];
    const float* beta2  = (const float*)d_in[6];
    const int*   src    = (const int*)d_in[7];
    const int*   dst    = (const int*)d_in[8];

    int n = in_sizes[2];
    int e = in_sizes[7];
    if (n > N_MAX) n = N_MAX;
    if (e > E_MAX) e = E_MAX;

    const int B = 256;
    const int GRID_PERSIST = 148 * 8;
    int scan_blocks = (n + SCAN_T - 1) / SCAN_T;   // 196 for n=100K (< SCAN_BMAX)

    // zero scratch via graph-capturable memset nodes (no kernel launches)
    void* p_deg = nullptr;
    void* p_state = nullptr;
    cudaGetSymbolAddress(&p_deg, g_deg);
    cudaGetSymbolAddress(&p_state, g_scan_state);
    cudaMemsetAsync(p_deg, 0, (size_t)n * sizeof(int));
    cudaMemsetAsync(p_state, 0, (size_t)SCAN_BMAX * sizeof(unsigned long long));

    deg_hin_kernel<<<GRID_PERSIST, B>>>(dst, (const float4*)h, norm, n, e); // L0
    scan_kernel<<<scan_blocks, SCAN_T>>>(n, e);                              // L1
    scatter_kernel<<<2048, B>>>(dst, src, e);                                // L2
    agg_kernel<<<GRID_PERSIST, B>>>((const float2*)ef, n);                   // L3 <- ncu
    pass2_kernel<<<GRID_PERSIST, B>>>(norm, gamma1, beta1, n);               // L4
    final_kernel<<<GRID_PERSIST, B>>>(norm, gamma1, beta1, gamma2, beta2,
                                      (float2*)d_out, n);                    // L5
}

// round 5
// speedup vs baseline: 1.5098x; 1.2236x over previous
#include <cuda_runtime.h>
#include <math.h>

// ---------------------------------------------------------------------------
// ActivationPNALayer: fused PNA aggregation + tower + 2x BatchNorm
//  0: h [N*D] f32   1: ef [E*D] f32   2: norm [N] f32
//  3: gamma1 [D]    4: beta1 [D]      5: gamma2 [D]    6: beta2 [D]
//  7: src [E] i32   8: dst [E] i32
// Output: [N*D] f32
// ---------------------------------------------------------------------------

#define N_MAX 100000
#define E_MAX 1600000
#define DD 64
#define AVG_D_LOG 2.8332133440562162f
#define EPS_STD 1e-5f
#define EPS_BN 1e-5f

#define SCAN_T 512
#define SCAN_BMAX 256

// scratch (device globals: allocation-free)
__device__ float g_hin[N_MAX * DD];
__device__ float g_ht[N_MAX * DD];
__device__ int   g_deg[N_MAX];
__device__ int   g_off[N_MAX + 1];
__device__ int   g_cur[N_MAX];
__device__ int2  g_epack[E_MAX];                  // {eid, src} per CSR slot
__device__ unsigned long long g_scan_state[SCAN_BMAX];
__device__ float g_s1[DD], g_s2[DD], g_t1[DD], g_t2[DD];

// ------------------------------------------------- degree count + h_in = h*norm
__global__ void __launch_bounds__(256) deg_hin_kernel(
    const int* __restrict__ dst, const float4* __restrict__ h4,
    const float* __restrict__ norm, int n, int e) {
    int total = gridDim.x * blockDim.x;
    int tid = blockIdx.x * blockDim.x + threadIdx.x;
    for (int i = tid; i < e; i += total)
        atomicAdd(&g_deg[dst[i]], 1);
    int nq = n * (DD / 4);
    float4* o4 = (float4*)g_hin;
    for (int i = tid; i < nq; i += total) {
        int row = i >> 4;
        float nv = __ldg(&norm[row]);
        float4 v = h4[i];
        v.x *= nv; v.y *= nv; v.z *= nv; v.w *= nv;
        o4[i] = v;
    }
}

// ------------------------------------------------- single-pass scan (lookback)
__global__ void __launch_bounds__(SCAN_T) scan_kernel(int n, int e_total) {
    __shared__ int sh[SCAN_T];
    __shared__ int sh_prefix;
    int bid = blockIdx.x, tid = threadIdx.x;
    int i = bid * SCAN_T + tid;
    int v = (i < n) ? g_deg[i] : 0;
    sh[tid] = v;
    __syncthreads();
    for (int s = 1; s < SCAN_T; s <<= 1) {
        int t = (tid >= s) ? sh[tid - s] : 0;
        __syncthreads();
        sh[tid] += t;
        __syncthreads();
    }
    int total = sh[SCAN_T - 1];

    if (tid == 0) {
        if (bid == 0) {
            sh_prefix = 0;
            atomicExch(&g_scan_state[0], (2ULL << 32) | (unsigned)total);
        } else {
            atomicExch(&g_scan_state[bid], (1ULL << 32) | (unsigned)total);
            unsigned long long prefix = 0;
            int j = bid - 1;
            while (true) {
                unsigned long long s = atomicAdd(&g_scan_state[j], 0ULL);
                unsigned f = (unsigned)(s >> 32);
                if (f == 2u) { prefix += (unsigned)s; break; }
                if (f == 1u) { prefix += (unsigned)s; j--; }
            }
            atomicExch(&g_scan_state[bid],
                       (2ULL << 32) | (unsigned)(prefix + (unsigned)total));
            sh_prefix = (int)prefix;
        }
    }
    if (bid == 0) {
        if (tid < DD) g_s1[tid] = 0.f;
        else if (tid < 2 * DD) g_s2[tid - DD] = 0.f;
        else if (tid < 3 * DD) g_t1[tid - 2 * DD] = 0.f;
        else if (tid < 4 * DD) g_t2[tid - 3 * DD] = 0.f;
    }
    __syncthreads();
    int excl = sh_prefix + sh[tid] - v;
    if (i < n) { g_off[i] = excl; g_cur[i] = excl; }
    if (i == 0) g_off[n] = e_total;
}

// ------------------------------------------------- CSR scatter (packed records)
__global__ void __launch_bounds__(256) scatter_kernel(
    const int* __restrict__ dst, const int* __restrict__ src, int e) {
    int total = gridDim.x * blockDim.x;
    for (int i = blockIdx.x * blockDim.x + threadIdx.x; i < e; i += total) {
        int d = dst[i];
        int pos = atomicAdd(&g_cur[d], 1);
        g_epack[pos] = make_int2(i, src[i]);
    }
}

// ------------------------------------------------- aggregation
// dim-per-thread: 64 threads (2 warps) per node, 4 nodes per 256-thread block.
// Low register pressure -> 8 blocks/SM -> ~2x bytes-in-flight vs float2 layout.
__global__ void __launch_bounds__(256, 8) agg_kernel(
    const float* __restrict__ ef, int n) {
    __shared__ int2 srec[8][32];
    const int lane = threadIdx.x & 31;
    const int w = threadIdx.x >> 5;               // warp in block (0..7)
    const int d = threadIdx.x & 63;               // dim owned by this thread
    const int slot = threadIdx.x >> 6;            // node slot in block (0..3)

    int node0 = blockIdx.x * 4 + slot;
    int nodeStride = gridDim.x * 4;

    const float* hin = g_hin;
    float* ht = g_ht;

    float a1 = 0.f, a2 = 0.f;                     // BN1 stats accum (dim d)

    for (int node = node0; node < n; node += nodeStride) {
        int start = g_off[node];
        int end = g_off[node + 1];
        float hd = hin[node * DD + d];

        float s = 0.f, q = 0.f;
        float mx = -INFINITY, mn = INFINITY;

        for (int base = start; base < end; base += 32) {
            int m = min(32, end - base);
            if (lane < m) srec[w][lane] = __ldcs(&g_epack[base + lane]);
            __syncwarp();
            #pragma unroll 4
            for (int j = 0; j < m; j++) {
                int2 r = srec[w][j];                       // LDS.64 broadcast
                float hs = hin[r.y * DD + d];
                float ev = __ldcs(&ef[r.x * DD + d]);
                float z = hd + hs + ev;
                s += z; q = fmaf(z, z, q);
                mx = fmaxf(mx, z); mn = fminf(mn, z);
            }
            __syncwarp();
        }

        float fdeg = (float)(end - start);
        float inv = 1.0f / fdeg;
        float mean = s * inv;
        float var = fmaxf(q * inv - mean * mean, 0.f);
        float sd = sqrtf(var + EPS_STD);
        float logd = logf(fdeg + 1.0f);
        float c = 1.0f + logd * (1.0f / AVG_D_LOG) + AVG_D_LOG / logd;
        float p = (hd + (mean + mx + mn + sd) * c) * (1.0f / 13.0f);
        ht[node * DD + d] = p;

        a1 += p; a2 = fmaf(p, p, a2);
    }

    // hierarchical BN1-stat reduction: regs -> shared -> global atomics
    __shared__ float sh1[DD], sh2[DD];
    if (threadIdx.x < DD) { sh1[threadIdx.x] = 0.f; sh2[threadIdx.x] = 0.f; }
    __syncthreads();
    atomicAdd(&sh1[d], a1);
    atomicAdd(&sh2[d], a2);
    __syncthreads();
    if (threadIdx.x < DD) {
        atomicAdd(&g_s1[threadIdx.x], sh1[threadIdx.x]);
        atomicAdd(&g_s2[threadIdx.x], sh2[threadIdx.x]);
    }
}

// ------------------------------------------------- BN2 stats
__global__ void __launch_bounds__(256) pass2_kernel(
    const float* __restrict__ norm, const float* __restrict__ gamma1,
    const float* __restrict__ beta1, int n) {
    int total = gridDim.x * blockDim.x;
    int p = threadIdx.x & 31;
    float invn = 1.0f / (float)n;
    float m0 = g_s1[2 * p] * invn, m1 = g_s1[2 * p + 1] * invn;
    float v0 = g_s2[2 * p] * invn - m0 * m0;
    float v1 = g_s2[2 * p + 1] * invn - m1 * m1;
    float A0 = __ldg(&gamma1[2 * p]) * rsqrtf(v0 + EPS_BN);
    float A1v = __ldg(&gamma1[2 * p + 1]) * rsqrtf(v1 + EPS_BN);
    float B0 = __ldg(&beta1[2 * p]) - m0 * A0;
    float B1v = __ldg(&beta1[2 * p + 1]) - m1 * A1v;

    const float2* ht2 = (const float2*)g_ht;
    float t1a = 0.f, t1b = 0.f, t2a = 0.f, t2b = 0.f;
    int nq = n * 32;
    for (int idx = blockIdx.x * blockDim.x + threadIdx.x; idx < nq; idx += total) {
        int row = idx >> 5;
        float nv = __ldg(&norm[row]);
        float2 h = ht2[idx];
        float y0 = fmaxf(fmaf(h.x, A0, B0) * nv, 0.f);
        float y1 = fmaxf(fmaf(h.y, A1v, B1v) * nv, 0.f);
        t1a += y0; t2a = fmaf(y0, y0, t2a);
        t1b += y1; t2b = fmaf(y1, y1, t2b);
    }
    __shared__ float sh1[DD], sh2[DD];
    if (threadIdx.x < DD) { sh1[threadIdx.x] = 0.f; sh2[threadIdx.x] = 0.f; }
    __syncthreads();
    atomicAdd(&sh1[2 * p], t1a);
    atomicAdd(&sh1[2 * p + 1], t1b);
    atomicAdd(&sh2[2 * p], t2a);
    atomicAdd(&sh2[2 * p + 1], t2b);
    __syncthreads();
    if (threadIdx.x < DD) {
        atomicAdd(&g_t1[threadIdx.x], sh1[threadIdx.x]);
        atomicAdd(&g_t2[threadIdx.x], sh2[threadIdx.x]);
    }
}

// ------------------------------------------------- final output
__global__ void __launch_bounds__(256) final_kernel(
    const float* __restrict__ norm, const float* __restrict__ gamma1,
    const float* __restrict__ beta1, const float* __restrict__ gamma2,
    const float* __restrict__ beta2, float2* __restrict__ out2, int n) {
    int total = gridDim.x * blockDim.x;
    int p = threadIdx.x & 31;
    float invn = 1.0f / (float)n;
    float m0 = g_s1[2 * p] * invn, m1 = g_s1[2 * p + 1] * invn;
    float v0 = g_s2[2 * p] * invn - m0 * m0;
    float v1 = g_s2[2 * p + 1] * invn - m1 * m1;
    float A0 = __ldg(&gamma1[2 * p]) * rsqrtf(v0 + EPS_BN);
    float A1v = __ldg(&gamma1[2 * p + 1]) * rsqrtf(v1 + EPS_BN);
    float B0 = __ldg(&beta1[2 * p]) - m0 * A0;
    float B1v = __ldg(&beta1[2 * p + 1]) - m1 * A1v;

    float n0 = g_t1[2 * p] * invn, n1 = g_t1[2 * p + 1] * invn;
    float w0 = g_t2[2 * p] * invn - n0 * n0;
    float w1 = g_t2[2 * p + 1] * invn - n1 * n1;
    float C0 = __ldg(&gamma2[2 * p]) * rsqrtf(w0 + EPS_BN);
    float C1 = __ldg(&gamma2[2 * p + 1]) * rsqrtf(w1 + EPS_BN);
    float D0 = __ldg(&beta2[2 * p]) - n0 * C0;
    float D1 = __ldg(&beta2[2 * p + 1]) - n1 * C1;

    const float2* ht2 = (const float2*)g_ht;
    int nq = n * 32;
    for (int idx = blockIdx.x * blockDim.x + threadIdx.x; idx < nq; idx += total) {
        int row = idx >> 5;
        float nv = __ldg(&norm[row]);
        float2 h = ht2[idx];
        float y0 = fmaxf(fmaf(h.x, A0, B0) * nv, 0.f);
        float y1 = fmaxf(fmaf(h.y, A1v, B1v) * nv, 0.f);
        out2[idx] = make_float2(fmaf(y0, C0, D0), fmaf(y1, C1, D1));
    }
}

// ---------------------------------------------------------------------------
extern "C" void kernel_launch(void* const* d_in, const int* in_sizes, int n_in,
                              void* d_out, int out_size) {
    const float* h      = (const float*)d_in[0];
    const float* ef     = (const float*)d_in[1];
    const float* norm   = (const float*)d_in[2];
    const float* gamma1 = (const float*)d_in[3];
    const float* beta1  = (const float*)d_in[4];
    const float* gamma2 = (const float*)d_in[5];
    const float* beta2  = (const float*)d_in[6];
    const int*   src    = (const int*)d_in[7];
    const int*   dst    = (const int*)d_in[8];

    int n = in_sizes[2];
    int e = in_sizes[7];
    if (n > N_MAX) n = N_MAX;
    if (e > E_MAX) e = E_MAX;

    const int B = 256;
    const int GRID_PERSIST = 148 * 8;              // one full wave @ 8 blocks/SM
    int scan_blocks = (n + SCAN_T - 1) / SCAN_T;

    void* p_deg = nullptr;
    void* p_state = nullptr;
    cudaGetSymbolAddress(&p_deg, g_deg);
    cudaGetSymbolAddress(&p_state, g_scan_state);
    cudaMemsetAsync(p_deg, 0, (size_t)n * sizeof(int));
    cudaMemsetAsync(p_state, 0, (size_t)SCAN_BMAX * sizeof(unsigned long long));

    deg_hin_kernel<<<GRID_PERSIST, B>>>(dst, (const float4*)h, norm, n, e);
    scan_kernel<<<scan_blocks, SCAN_T>>>(n, e);
    scatter_kernel<<<2048, B>>>(dst, src, e);
    agg_kernel<<<GRID_PERSIST, B>>>(ef, n);
    pass2_kernel<<<GRID_PERSIST, B>>>(norm, gamma1, beta1, n);
    final_kernel<<<GRID_PERSIST, B>>>(norm, gamma1, beta1, gamma2, beta2,
                                      (float2*)d_out, n);
}

// round 6
// speedup vs baseline: 1.6445x; 1.0892x over previous
#include <cuda_runtime.h>
#include <math.h>

// ---------------------------------------------------------------------------
// ActivationPNALayer: fused PNA aggregation + tower + 2x BatchNorm
//  0: h [N*D] f32   1: ef [E*D] f32   2: norm [N] f32
//  3: gamma1 [D]    4: beta1 [D]      5: gamma2 [D]    6: beta2 [D]
//  7: src [E] i32   8: dst [E] i32
// Output: [N*D] f32
// ---------------------------------------------------------------------------

#define N_MAX 100000
#define E_MAX 1600000
#define DD 64
#define AVG_D_LOG 2.8332133440562162f
#define EPS_STD 1e-5f
#define EPS_BN 1e-5f

#define SCAN_T 512
#define SCAN_BMAX 256

// scratch (device globals: allocation-free)
__device__ float g_hin[N_MAX * DD];
__device__ float g_ht[N_MAX * DD];
__device__ int   g_deg[N_MAX];
__device__ int   g_off[N_MAX + 1];
__device__ int   g_cur[N_MAX];
__device__ int2  g_epack[E_MAX];                  // {eid, src} per CSR slot
__device__ unsigned long long g_scan_state[SCAN_BMAX];
__device__ float g_s1[DD], g_s2[DD], g_t1[DD], g_t2[DD];
__device__ int   g_bar;                           // grid barrier counter

// ------------------------------------------------- degree count + h_in = h*norm
__global__ void __launch_bounds__(256) deg_hin_kernel(
    const int* __restrict__ dst, const float4* __restrict__ h4,
    const float* __restrict__ norm, int n, int e) {
    int total = gridDim.x * blockDim.x;
    int tid = blockIdx.x * blockDim.x + threadIdx.x;
    for (int i = tid; i < e; i += total)
        atomicAdd(&g_deg[dst[i]], 1);
    int nq = n * (DD / 4);
    float4* o4 = (float4*)g_hin;
    for (int i = tid; i < nq; i += total) {
        int row = i >> 4;
        float nv = __ldg(&norm[row]);
        float4 v = h4[i];
        v.x *= nv; v.y *= nv; v.z *= nv; v.w *= nv;
        o4[i] = v;
    }
}

// ------------------------------------------------- single-pass scan (lookback)
__global__ void __launch_bounds__(SCAN_T) scan_kernel(int n, int e_total) {
    __shared__ int sh[SCAN_T];
    __shared__ int sh_prefix;
    int bid = blockIdx.x, tid = threadIdx.x;
    int i = bid * SCAN_T + tid;
    int v = (i < n) ? g_deg[i] : 0;
    sh[tid] = v;
    __syncthreads();
    for (int s = 1; s < SCAN_T; s <<= 1) {
        int t = (tid >= s) ? sh[tid - s] : 0;
        __syncthreads();
        sh[tid] += t;
        __syncthreads();
    }
    int total = sh[SCAN_T - 1];

    if (tid == 0) {
        if (bid == 0) {
            sh_prefix = 0;
            atomicExch(&g_scan_state[0], (2ULL << 32) | (unsigned)total);
        } else {
            atomicExch(&g_scan_state[bid], (1ULL << 32) | (unsigned)total);
            unsigned long long prefix = 0;
            int j = bid - 1;
            while (true) {
                unsigned long long s = atomicAdd(&g_scan_state[j], 0ULL);
                unsigned f = (unsigned)(s >> 32);
                if (f == 2u) { prefix += (unsigned)s; break; }
                if (f == 1u) { prefix += (unsigned)s; j--; }
            }
            atomicExch(&g_scan_state[bid],
                       (2ULL << 32) | (unsigned)(prefix + (unsigned)total));
            sh_prefix = (int)prefix;
        }
    }
    if (bid == 0) {   // zero BN-stat accumulators for downstream kernels
        if (tid < DD) g_s1[tid] = 0.f;
        else if (tid < 2 * DD) g_s2[tid - DD] = 0.f;
        else if (tid < 3 * DD) g_t1[tid - 2 * DD] = 0.f;
        else if (tid < 4 * DD) g_t2[tid - 3 * DD] = 0.f;
    }
    __syncthreads();
    int excl = sh_prefix + sh[tid] - v;
    if (i < n) { g_off[i] = excl; g_cur[i] = excl; }
    if (i == 0) g_off[n] = e_total;
}

// ------------------------------------------------- CSR scatter (packed records)
__global__ void __launch_bounds__(256) scatter_kernel(
    const int* __restrict__ dst, const int* __restrict__ src, int e) {
    int total = gridDim.x * blockDim.x;
    for (int i = blockIdx.x * blockDim.x + threadIdx.x; i < e; i += total) {
        int d = dst[i];
        int pos = atomicAdd(&g_cur[d], 1);
        g_epack[pos] = make_int2(i, src[i]);
    }
}

// ------------------------------------------------- aggregation
// warp-per-node, lane owns dims (2*lane, 2*lane+1) as float2.
// launch_bounds(256,8) forces <=32 regs -> 8 blocks/SM resident.
// No BN work here (moved to bn_fused), keeping register pressure minimal.
__global__ void __launch_bounds__(256, 8) agg_kernel(
    const float2* __restrict__ ef2, int n) {
    __shared__ int2 srec[8][32];
    const int lane = threadIdx.x & 31;
    const int w = threadIdx.x >> 5;               // warp in block = node slot

    int node0 = blockIdx.x * 8 + w;
    int nodeStride = gridDim.x * 8;

    const float2* hin2 = (const float2*)g_hin;
    float2* ht2 = (float2*)g_ht;

    for (int node = node0; node < n; node += nodeStride) {
        int start = g_off[node];
        int end = g_off[node + 1];
        float2 hd = hin2[node * 32 + lane];

        float s0 = 0.f, s1 = 0.f, q0 = 0.f, q1 = 0.f;
        float mx0 = -INFINITY, mx1 = -INFINITY;
        float mn0 = INFINITY, mn1 = INFINITY;

        for (int base = start; base < end; base += 32) {
            int m = min(32, end - base);
            if (lane < m) srec[w][lane] = __ldcs(&g_epack[base + lane]);
            __syncwarp();
            #pragma unroll 4
            for (int j = 0; j < m; j++) {
                int2 r = srec[w][j];                        // LDS.64 broadcast
                float2 hs = hin2[r.y * 32 + lane];
                float2 ev = __ldcs(&ef2[r.x * 32 + lane]);
                float z0 = hd.x + hs.x + ev.x;
                float z1 = hd.y + hs.y + ev.y;
                s0 += z0; q0 = fmaf(z0, z0, q0);
                mx0 = fmaxf(mx0, z0); mn0 = fminf(mn0, z0);
                s1 += z1; q1 = fmaf(z1, z1, q1);
                mx1 = fmaxf(mx1, z1); mn1 = fminf(mn1, z1);
            }
            __syncwarp();
        }

        float fdeg = (float)(end - start);
        float inv = 1.0f / fdeg;
        float mean0 = s0 * inv, mean1 = s1 * inv;
        float var0 = fmaxf(q0 * inv - mean0 * mean0, 0.f);
        float var1 = fmaxf(q1 * inv - mean1 * mean1, 0.f);
        float std0 = sqrtf(var0 + EPS_STD);
        float std1 = sqrtf(var1 + EPS_STD);
        float logd = logf(fdeg + 1.0f);
        float c = 1.0f + logd * (1.0f / AVG_D_LOG) + AVG_D_LOG / logd;
        float p0 = (hd.x + (mean0 + mx0 + mn0 + std0) * c) * (1.0f / 13.0f);
        float p1 = (hd.y + (mean1 + mx1 + mn1 + std1) * c) * (1.0f / 13.0f);
        ht2[node * 32 + lane] = make_float2(p0, p1);
    }
}

// ------------------------------------------------- fused BN1-stats / BN2 / out
// Persistent grid (148*8 blocks, launch_bounds(256,8) => all resident) with
// software grid barriers. ht stays L2-resident across the three passes.
__device__ __forceinline__ void grid_barrier(int target) {
    __syncthreads();
    if (threadIdx.x == 0) {
        __threadfence();
        atomicAdd(&g_bar, 1);
        while (atomicAdd(&g_bar, 0) < target) __nanosleep(64);
    }
    __syncthreads();
}

__global__ void __launch_bounds__(256, 8) bn_fused_kernel(
    const float* __restrict__ norm, const float* __restrict__ gamma1,
    const float* __restrict__ beta1, const float* __restrict__ gamma2,
    const float* __restrict__ beta2, float4* __restrict__ out4, int n) {
    const int tid = threadIdx.x;
    const int stride = gridDim.x * blockDim.x;       // multiple of 16
    const int idx0 = blockIdx.x * blockDim.x + tid;
    const int g = (idx0 & 15) * 4;                   // this thread's dim group
    const int nq4 = n * (DD / 4);
    const float4* ht4 = (const float4*)g_ht;

    __shared__ float sh1[DD], sh2[DD];

    // ---- pass 1: BN1 batch stats from ht ----
    float s1a = 0.f, s1b = 0.f, s1c = 0.f, s1d = 0.f;
    float s2a = 0.f, s2b = 0.f, s2c = 0.f, s2d = 0.f;
    for (int idx = idx0; idx < nq4; idx += stride) {
        float4 p = ht4[idx];
        s1a += p.x; s2a = fmaf(p.x, p.x, s2a);
        s1b += p.y; s2b = fmaf(p.y, p.y, s2b);
        s1c += p.z; s2c = fmaf(p.z, p.z, s2c);
        s1d += p.w; s2d = fmaf(p.w, p.w, s2d);
    }
    if (tid < DD) { sh1[tid] = 0.f; sh2[tid] = 0.f; }
    __syncthreads();
    atomicAdd(&sh1[g + 0], s1a); atomicAdd(&sh2[g + 0], s2a);
    atomicAdd(&sh1[g + 1], s1b); atomicAdd(&sh2[g + 1], s2b);
    atomicAdd(&sh1[g + 2], s1c); atomicAdd(&sh2[g + 2], s2c);
    atomicAdd(&sh1[g + 3], s1d); atomicAdd(&sh2[g + 3], s2d);
    __syncthreads();
    if (tid < DD) {
        atomicAdd(&g_s1[tid], sh1[tid]);
        atomicAdd(&g_s2[tid], sh2[tid]);
    }
    grid_barrier(gridDim.x);

    // ---- BN1 affine for this thread's 4 dims ----
    float invn = 1.0f / (float)n;
    float A[4], Bc[4];
    #pragma unroll
    for (int k = 0; k < 4; k++) {
        float m = g_s1[g + k] * invn;
        float v = g_s2[g + k] * invn - m * m;
        A[k] = __ldg(&gamma1[g + k]) * rsqrtf(v + EPS_BN);
        Bc[k] = __ldg(&beta1[g + k]) - m * A[k];
    }

    // ---- pass 2: y = relu((ht*A+B)*norm), BN2 stats ----
    float t1a = 0.f, t1b = 0.f, t1c = 0.f, t1d = 0.f;
    float t2a = 0.f, t2b = 0.f, t2c = 0.f, t2d = 0.f;
    for (int idx = idx0; idx < nq4; idx += stride) {
        float nv = __ldg(&norm[idx >> 4]);
        float4 p = ht4[idx];
        float y0 = fmaxf(fmaf(p.x, A[0], Bc[0]) * nv, 0.f);
        float y1 = fmaxf(fmaf(p.y, A[1], Bc[1]) * nv, 0.f);
        float y2 = fmaxf(fmaf(p.z, A[2], Bc[2]) * nv, 0.f);
        float y3 = fmaxf(fmaf(p.w, A[3], Bc[3]) * nv, 0.f);
        t1a += y0; t2a = fmaf(y0, y0, t2a);
        t1b += y1; t2b = fmaf(y1, y1, t2b);
        t1c += y2; t2c = fmaf(y2, y2, t2c);
        t1d += y3; t2d = fmaf(y3, y3, t2d);
    }
    __syncthreads();
    if (tid < DD) { sh1[tid] = 0.f; sh2[tid] = 0.f; }
    __syncthreads();
    atomicAdd(&sh1[g + 0], t1a); atomicAdd(&sh2[g + 0], t2a);
    atomicAdd(&sh1[g + 1], t1b); atomicAdd(&sh2[g + 1], t2b);
    atomicAdd(&sh1[g + 2], t1c); atomicAdd(&sh2[g + 2], t2c);
    atomicAdd(&sh1[g + 3], t1d); atomicAdd(&sh2[g + 3], t2d);
    __syncthreads();
    if (tid < DD) {
        atomicAdd(&g_t1[tid], sh1[tid]);
        atomicAdd(&g_t2[tid], sh2[tid]);
    }
    grid_barrier(2 * gridDim.x);

    // ---- BN2 affine ----
    float C[4], Dc[4];
    #pragma unroll
    for (int k = 0; k < 4; k++) {
        float m = g_t1[g + k] * invn;
        float v = g_t2[g + k] * invn - m * m;
        C[k] = __ldg(&gamma2[g + k]) * rsqrtf(v + EPS_BN);
        Dc[k] = __ldg(&beta2[g + k]) - m * C[k];
    }

    // ---- pass 3: output ----
    for (int idx = idx0; idx < nq4; idx += stride) {
        float nv = __ldg(&norm[idx >> 4]);
        float4 p = ht4[idx];
        float y0 = fmaxf(fmaf(p.x, A[0], Bc[0]) * nv, 0.f);
        float y1 = fmaxf(fmaf(p.y, A[1], Bc[1]) * nv, 0.f);
        float y2 = fmaxf(fmaf(p.z, A[2], Bc[2]) * nv, 0.f);
        float y3 = fmaxf(fmaf(p.w, A[3], Bc[3]) * nv, 0.f);
        float4 o;
        o.x = fmaf(y0, C[0], Dc[0]);
        o.y = fmaf(y1, C[1], Dc[1]);
        o.z = fmaf(y2, C[2], Dc[2]);
        o.w = fmaf(y3, C[3], Dc[3]);
        out4[idx] = o;
    }
}

// ---------------------------------------------------------------------------
extern "C" void kernel_launch(void* const* d_in, const int* in_sizes, int n_in,
                              void* d_out, int out_size) {
    const float* h      = (const float*)d_in[0];
    const float* ef     = (const float*)d_in[1];
    const float* norm   = (const float*)d_in[2];
    const float* gamma1 = (const float*)d_in[3];
    const float* beta1  = (const float*)d_in[4];
    const float* gamma2 = (const float*)d_in[5];
    const float* beta2  = (const float*)d_in[6];
    const int*   src    = (const int*)d_in[7];
    const int*   dst    = (const int*)d_in[8];

    int n = in_sizes[2];
    int e = in_sizes[7];
    if (n > N_MAX) n = N_MAX;
    if (e > E_MAX) e = E_MAX;

    const int B = 256;
    const int GRID_PERSIST = 148 * 8;              // one full resident wave
    int scan_blocks = (n + SCAN_T - 1) / SCAN_T;

    void *p_deg = nullptr, *p_state = nullptr, *p_bar = nullptr;
    cudaGetSymbolAddress(&p_deg, g_deg);
    cudaGetSymbolAddress(&p_state, g_scan_state);
    cudaGetSymbolAddress(&p_bar, g_bar);
    cudaMemsetAsync(p_deg, 0, (size_t)n * sizeof(int));
    cudaMemsetAsync(p_state, 0, (size_t)SCAN_BMAX * sizeof(unsigned long long));
    cudaMemsetAsync(p_bar, 0, sizeof(int));

    deg_hin_kernel<<<GRID_PERSIST, B>>>(dst, (const float4*)h, norm, n, e);
    scan_kernel<<<scan_blocks, SCAN_T>>>(n, e);
    scatter_kernel<<<2048, B>>>(dst, src, e);
    agg_kernel<<<GRID_PERSIST, B>>>((const float2*)ef, n);
    bn_fused_kernel<<<GRID_PERSIST, B>>>(norm, gamma1, beta1, gamma2, beta2,
                                         (float4*)d_out, n);
}

// round 7
// speedup vs baseline: 1.6852x; 1.0247x over previous
#include <cuda_runtime.h>
#include <math.h>

// ---------------------------------------------------------------------------
// ActivationPNALayer: fused PNA aggregation + tower + 2x BatchNorm
//  0: h [N*D] f32   1: ef [E*D] f32   2: norm [N] f32
//  3: gamma1 [D]    4: beta1 [D]      5: gamma2 [D]    6: beta2 [D]
//  7: src [E] i32   8: dst [E] i32
// Output: [N*D] f32
// ---------------------------------------------------------------------------

#define N_MAX 100000
#define E_MAX 1600000
#define DD 64
#define AVG_D_LOG 2.8332133440562162f
#define EPS_STD 1e-5f
#define EPS_BN 1e-5f

#define SCAN_T 512
#define SCAN_BMAX 256

// scratch (device globals: allocation-free)
__device__ float g_hin[N_MAX * DD];
__device__ float g_ht[N_MAX * DD];
__device__ int   g_deg[N_MAX];
__device__ int   g_off[N_MAX + 1];
__device__ int   g_cur[N_MAX];
__device__ int2  g_epack[E_MAX];                  // {eid, src} per CSR slot
__device__ unsigned long long g_scan_state[SCAN_BMAX];
__device__ float g_s1[DD], g_s2[DD], g_t1[DD], g_t2[DD];
__device__ int   g_bar;                           // grid barrier counter

// ------------------------------------------------- degree count + h_in = h*norm
__global__ void __launch_bounds__(256) deg_hin_kernel(
    const int* __restrict__ dst, const float4* __restrict__ h4,
    const float* __restrict__ norm, int n, int e) {
    int total = gridDim.x * blockDim.x;
    int tid = blockIdx.x * blockDim.x + threadIdx.x;
    for (int i = tid; i < e; i += total)
        atomicAdd(&g_deg[dst[i]], 1);
    int nq = n * (DD / 4);
    float4* o4 = (float4*)g_hin;
    for (int i = tid; i < nq; i += total) {
        int row = i >> 4;
        float nv = __ldg(&norm[row]);
        float4 v = h4[i];
        v.x *= nv; v.y *= nv; v.z *= nv; v.w *= nv;
        o4[i] = v;
    }
}

// ------------------------------------------------- single-pass scan (lookback)
__global__ void __launch_bounds__(SCAN_T) scan_kernel(int n, int e_total) {
    __shared__ int sh[SCAN_T];
    __shared__ int sh_prefix;
    int bid = blockIdx.x, tid = threadIdx.x;
    int i = bid * SCAN_T + tid;
    int v = (i < n) ? g_deg[i] : 0;
    sh[tid] = v;
    __syncthreads();
    for (int s = 1; s < SCAN_T; s <<= 1) {
        int t = (tid >= s) ? sh[tid - s] : 0;
        __syncthreads();
        sh[tid] += t;
        __syncthreads();
    }
    int total = sh[SCAN_T - 1];

    if (tid == 0) {
        if (bid == 0) {
            sh_prefix = 0;
            atomicExch(&g_scan_state[0], (2ULL << 32) | (unsigned)total);
        } else {
            atomicExch(&g_scan_state[bid], (1ULL << 32) | (unsigned)total);
            unsigned long long prefix = 0;
            int j = bid - 1;
            while (true) {
                unsigned long long s = atomicAdd(&g_scan_state[j], 0ULL);
                unsigned f = (unsigned)(s >> 32);
                if (f == 2u) { prefix += (unsigned)s; break; }
                if (f == 1u) { prefix += (unsigned)s; j--; }
            }
            atomicExch(&g_scan_state[bid],
                       (2ULL << 32) | (unsigned)(prefix + (unsigned)total));
            sh_prefix = (int)prefix;
        }
    }
    if (bid == 0) {   // zero BN-stat accumulators for downstream kernels
        if (tid < DD) g_s1[tid] = 0.f;
        else if (tid < 2 * DD) g_s2[tid - DD] = 0.f;
        else if (tid < 3 * DD) g_t1[tid - 2 * DD] = 0.f;
        else if (tid < 4 * DD) g_t2[tid - 3 * DD] = 0.f;
    }
    __syncthreads();
    int excl = sh_prefix + sh[tid] - v;
    if (i < n) { g_off[i] = excl; g_cur[i] = excl; }
    if (i == 0) g_off[n] = e_total;
}

// ------------------------------------------------- CSR scatter (packed records)
__global__ void __launch_bounds__(256) scatter_kernel(
    const int* __restrict__ dst, const int* __restrict__ src, int e) {
    int total = gridDim.x * blockDim.x;
    for (int i = blockIdx.x * blockDim.x + threadIdx.x; i < e; i += total) {
        int d = dst[i];
        int pos = atomicAdd(&g_cur[d], 1);
        g_epack[pos] = make_int2(i, src[i]);
    }
}

// ------------------------------------------------- aggregation
// warp-per-node, lane owns dims (2*lane, 2*lane+1) as float2.
// CSR records broadcast-loaded: all lanes LDG the same g_epack[k] (one 8B
// request, L1 line covers 16 records). No shared staging, no syncwarp,
// no predication in the hot loop.
__global__ void __launch_bounds__(256, 8) agg_kernel(
    const float2* __restrict__ ef2, int n) {
    const int lane = threadIdx.x & 31;
    const int w = threadIdx.x >> 5;               // warp in block = node slot

    int node0 = blockIdx.x * 8 + w;
    int nodeStride = gridDim.x * 8;

    const float2* hin2 = (const float2*)g_hin;
    float2* ht2 = (float2*)g_ht;

    for (int node = node0; node < n; node += nodeStride) {
        int start = g_off[node];
        int end = g_off[node + 1];
        float2 hd = hin2[node * 32 + lane];

        float s0 = 0.f, s1 = 0.f, q0 = 0.f, q1 = 0.f;
        float mx0 = -INFINITY, mx1 = -INFINITY;
        float mn0 = INFINITY, mn1 = INFINITY;

        #pragma unroll 4
        for (int k = start; k < end; k++) {
            int2 r = __ldg(&g_epack[k]);                 // warp-broadcast LDG
            float2 hs = hin2[r.y * 32 + lane];
            float2 ev = __ldcs(&ef2[r.x * 32 + lane]);
            float z0 = hd.x + hs.x + ev.x;
            float z1 = hd.y + hs.y + ev.y;
            s0 += z0; q0 = fmaf(z0, z0, q0);
            mx0 = fmaxf(mx0, z0); mn0 = fminf(mn0, z0);
            s1 += z1; q1 = fmaf(z1, z1, q1);
            mx1 = fmaxf(mx1, z1); mn1 = fminf(mn1, z1);
        }

        float fdeg = (float)(end - start);
        float inv = 1.0f / fdeg;
        float mean0 = s0 * inv, mean1 = s1 * inv;
        float var0 = fmaxf(q0 * inv - mean0 * mean0, 0.f);
        float var1 = fmaxf(q1 * inv - mean1 * mean1, 0.f);
        float std0 = sqrtf(var0 + EPS_STD);
        float std1 = sqrtf(var1 + EPS_STD);
        float logd = logf(fdeg + 1.0f);
        float c = 1.0f + logd * (1.0f / AVG_D_LOG) + AVG_D_LOG / logd;
        float p0 = (hd.x + (mean0 + mx0 + mn0 + std0) * c) * (1.0f / 13.0f);
        float p1 = (hd.y + (mean1 + mx1 + mn1 + std1) * c) * (1.0f / 13.0f);
        ht2[node * 32 + lane] = make_float2(p0, p1);
    }
}

// ------------------------------------------------- fused BN1-stats / BN2 / out
// Persistent grid (148*8 blocks, launch_bounds(256,8) => all resident) with
// software grid barriers. ht stays L2-resident across the three passes.
__device__ __forceinline__ void grid_barrier(int target) {
    __syncthreads();
    if (threadIdx.x == 0) {
        __threadfence();
        atomicAdd(&g_bar, 1);
        while (atomicAdd(&g_bar, 0) < target) __nanosleep(64);
    }
    __syncthreads();
}

__global__ void __launch_bounds__(256, 8) bn_fused_kernel(
    const float* __restrict__ norm, const float* __restrict__ gamma1,
    const float* __restrict__ beta1, const float* __restrict__ gamma2,
    const float* __restrict__ beta2, float4* __restrict__ out4, int n) {
    const int tid = threadIdx.x;
    const int stride = gridDim.x * blockDim.x;       // multiple of 16
    const int idx0 = blockIdx.x * blockDim.x + tid;
    const int g = (idx0 & 15) * 4;                   // this thread's dim group
    const int nq4 = n * (DD / 4);
    const float4* ht4 = (const float4*)g_ht;

    __shared__ float sh1[DD], sh2[DD];

    // ---- pass 1: BN1 batch stats from ht ----
    float s1a = 0.f, s1b = 0.f, s1c = 0.f, s1d = 0.f;
    float s2a = 0.f, s2b = 0.f, s2c = 0.f, s2d = 0.f;
    for (int idx = idx0; idx < nq4; idx += stride) {
        float4 p = ht4[idx];
        s1a += p.x; s2a = fmaf(p.x, p.x, s2a);
        s1b += p.y; s2b = fmaf(p.y, p.y, s2b);
        s1c += p.z; s2c = fmaf(p.z, p.z, s2c);
        s1d += p.w; s2d = fmaf(p.w, p.w, s2d);
    }
    if (tid < DD) { sh1[tid] = 0.f; sh2[tid] = 0.f; }
    __syncthreads();
    atomicAdd(&sh1[g + 0], s1a); atomicAdd(&sh2[g + 0], s2a);
    atomicAdd(&sh1[g + 1], s1b); atomicAdd(&sh2[g + 1], s2b);
    atomicAdd(&sh1[g + 2], s1c); atomicAdd(&sh2[g + 2], s2c);
    atomicAdd(&sh1[g + 3], s1d); atomicAdd(&sh2[g + 3], s2d);
    __syncthreads();
    if (tid < DD) {
        atomicAdd(&g_s1[tid], sh1[tid]);
        atomicAdd(&g_s2[tid], sh2[tid]);
    }
    grid_barrier(gridDim.x);

    // ---- BN1 affine for this thread's 4 dims ----
    float invn = 1.0f / (float)n;
    float A[4], Bc[4];
    #pragma unroll
    for (int k = 0; k < 4; k++) {
        float m = g_s1[g + k] * invn;
        float v = g_s2[g + k] * invn - m * m;
        A[k] = __ldg(&gamma1[g + k]) * rsqrtf(v + EPS_BN);
        Bc[k] = __ldg(&beta1[g + k]) - m * A[k];
    }

    // ---- pass 2: y = relu((ht*A+B)*norm), BN2 stats ----
    float t1a = 0.f, t1b = 0.f, t1c = 0.f, t1d = 0.f;
    float t2a = 0.f, t2b = 0.f, t2c = 0.f, t2d = 0.f;
    for (int idx = idx0; idx < nq4; idx += stride) {
        float nv = __ldg(&norm[idx >> 4]);
        float4 p = ht4[idx];
        float y0 = fmaxf(fmaf(p.x, A[0], Bc[0]) * nv, 0.f);
        float y1 = fmaxf(fmaf(p.y, A[1], Bc[1]) * nv, 0.f);
        float y2 = fmaxf(fmaf(p.z, A[2], Bc[2]) * nv, 0.f);
        float y3 = fmaxf(fmaf(p.w, A[3], Bc[3]) * nv, 0.f);
        t1a += y0; t2a = fmaf(y0, y0, t2a);
        t1b += y1; t2b = fmaf(y1, y1, t2b);
        t1c += y2; t2c = fmaf(y2, y2, t2c);
        t1d += y3; t2d = fmaf(y3, y3, t2d);
    }
    __syncthreads();
    if (tid < DD) { sh1[tid] = 0.f; sh2[tid] = 0.f; }
    __syncthreads();
    atomicAdd(&sh1[g + 0], t1a); atomicAdd(&sh2[g + 0], t2a);
    atomicAdd(&sh1[g + 1], t1b); atomicAdd(&sh2[g + 1], t2b);
    atomicAdd(&sh1[g + 2], t1c); atomicAdd(&sh2[g + 2], t2c);
    atomicAdd(&sh1[g + 3], t1d); atomicAdd(&sh2[g + 3], t2d);
    __syncthreads();
    if (tid < DD) {
        atomicAdd(&g_t1[tid], sh1[tid]);
        atomicAdd(&g_t2[tid], sh2[tid]);
    }
    grid_barrier(2 * gridDim.x);

    // ---- BN2 affine ----
    float C[4], Dc[4];
    #pragma unroll
    for (int k = 0; k < 4; k++) {
        float m = g_t1[g + k] * invn;
        float v = g_t2[g + k] * invn - m * m;
        C[k] = __ldg(&gamma2[g + k]) * rsqrtf(v + EPS_BN);
        Dc[k] = __ldg(&beta2[g + k]) - m * C[k];
    }

    // ---- pass 3: output ----
    for (int idx = idx0; idx < nq4; idx += stride) {
        float nv = __ldg(&norm[idx >> 4]);
        float4 p = ht4[idx];
        float y0 = fmaxf(fmaf(p.x, A[0], Bc[0]) * nv, 0.f);
        float y1 = fmaxf(fmaf(p.y, A[1], Bc[1]) * nv, 0.f);
        float y2 = fmaxf(fmaf(p.z, A[2], Bc[2]) * nv, 0.f);
        float y3 = fmaxf(fmaf(p.w, A[3], Bc[3]) * nv, 0.f);
        float4 o;
        o.x = fmaf(y0, C[0], Dc[0]);
        o.y = fmaf(y1, C[1], Dc[1]);
        o.z = fmaf(y2, C[2], Dc[2]);
        o.w = fmaf(y3, C[3], Dc[3]);
        out4[idx] = o;
    }
}

// ---------------------------------------------------------------------------
extern "C" void kernel_launch(void* const* d_in, const int* in_sizes, int n_in,
                              void* d_out, int out_size) {
    const float* h      = (const float*)d_in[0];
    const float* ef     = (const float*)d_in[1];
    const float* norm   = (const float*)d_in[2];
    const float* gamma1 = (const float*)d_in[3];
    const float* beta1  = (const float*)d_in[4];
    const float* gamma2 = (const float*)d_in[5];
    const float* beta2  = (const float*)d_in[6];
    const int*   src    = (const int*)d_in[7];
    const int*   dst    = (const int*)d_in[8];

    int n = in_sizes[2];
    int e = in_sizes[7];
    if (n > N_MAX) n = N_MAX;
    if (e > E_MAX) e = E_MAX;

    const int B = 256;
    const int GRID_PERSIST = 148 * 8;              // one full resident wave
    int scan_blocks = (n + SCAN_T - 1) / SCAN_T;

    void *p_deg = nullptr, *p_state = nullptr, *p_bar = nullptr;
    cudaGetSymbolAddress(&p_deg, g_deg);
    cudaGetSymbolAddress(&p_state, g_scan_state);
    cudaGetSymbolAddress(&p_bar, g_bar);
    cudaMemsetAsync(p_deg, 0, (size_t)n * sizeof(int));
    cudaMemsetAsync(p_state, 0, (size_t)SCAN_BMAX * sizeof(unsigned long long));
    cudaMemsetAsync(p_bar, 0, sizeof(int));

    deg_hin_kernel<<<GRID_PERSIST, B>>>(dst, (const float4*)h, norm, n, e);
    scan_kernel<<<scan_blocks, SCAN_T>>>(n, e);
    scatter_kernel<<<2048, B>>>(dst, src, e);
    agg_kernel<<<GRID_PERSIST, B>>>((const float2*)ef, n);
    bn_fused_kernel<<<GRID_PERSIST, B>>>(norm, gamma1, beta1, gamma2, beta2,
                                         (float4*)d_out, n);
}